// round 11
// baseline (speedup 1.0000x reference)
#include <cuda_runtime.h>
#include <cuda_fp16.h>
#include <cstdint>

#define Nn 10000
#define Ee 320000

typedef unsigned long long ull;
typedef unsigned int u32;

// ---------------- device scratch ----------------
__device__ float g_aggH[Nn * 256];
__device__ float g_aggC[Nn * 3];
__device__ float g_cnt[Nn];
__device__ __align__(16) float g_P[(size_t)Nn * 512];
// mma-fragment-ordered weights: [t=n16 tile 0..15][kq=k16 0..15][lane 0..31] uint4
__device__ __align__(16) uint4 g_F2h[8192];
__device__ __align__(16) uint4 g_F2l[8192];
__device__ __align__(16) uint4 g_Fch[8192];

// ---------------- helpers ----------------
__device__ __forceinline__ u32 smem_u32(const void* p) {
    u32 a;
    asm("{ .reg .u64 t; cvta.to.shared.u64 t, %1; cvt.u32.u64 %0, t; }" : "=r"(a) : "l"(p));
    return a;
}
__device__ __forceinline__ void ldsm4(u32* r, u32 addr) {
    asm volatile("ldmatrix.sync.aligned.m8n8.x4.shared.b16 {%0,%1,%2,%3},[%4];"
                 : "=r"(r[0]), "=r"(r[1]), "=r"(r[2]), "=r"(r[3]) : "r"(addr));
}
__device__ __forceinline__ void mma16816(float* d, const u32* a, const u32* b) {
    asm volatile(
        "mma.sync.aligned.m16n8k16.row.col.f32.f16.f16.f32 "
        "{%0,%1,%2,%3},{%4,%5,%6,%7},{%8,%9},{%0,%1,%2,%3};"
        : "+f"(d[0]), "+f"(d[1]), "+f"(d[2]), "+f"(d[3])
        : "r"(a[0]), "r"(a[1]), "r"(a[2]), "r"(a[3]), "r"(b[0]), "r"(b[1]));
}

// MUFU-free silu
__device__ __forceinline__ float silu_fast(float x) {
    float v = fmaxf(-fabsf(x) * 1.4426950408889634f, -30.0f);
    float r = v + 12582912.0f;
    int ni = __float_as_int(r) - 0x4B400000;
    float f = v - (r - 12582912.0f);
    float p = 1.3333558146e-3f;
    p = fmaf(p, f, 9.6181291076e-3f);
    p = fmaf(p, f, 5.5504108664e-2f);
    p = fmaf(p, f, 2.4015967802e-1f);
    p = fmaf(p, f, 6.9314718056e-1f);
    p = fmaf(p, f, 1.0f);
    float z = __int_as_float(__float_as_int(p) + (ni << 23));
    float d = 1.0f + z;
    float y = __int_as_float(0x7EF311C3 - __float_as_int(d));
    y = y * fmaf(-d, y, 2.0f);
    y = y * fmaf(-d, y, 2.0f);
    y = y * fmaf(-d, y, 2.0f);
    float sig = (x >= 0.0f) ? y : (1.0f - y);
    return x * sig;
}

// ---------------- fp32 FFMA2 GEMM pieces ----------------
__device__ __forceinline__ ull pack_dup(float a) { ull r; asm("mov.b64 %0,{%1,%1};" : "=l"(r) : "f"(a)); return r; }
__device__ __forceinline__ float2 unpack2(ull v) { float2 r; asm("mov.b64 {%0,%1},%2;" : "=f"(r.x), "=f"(r.y) : "l"(v)); return r; }
__device__ __forceinline__ void fma2(ull& d, ull a, ull b) { asm("fma.rn.f32x2 %0,%1,%2,%0;" : "+l"(d) : "l"(a), "l"(b)); }

template <int AS>
__device__ __forceinline__ void mma_chunk(const float* __restrict__ A, const float* __restrict__ B,
                                          ull acc[4][8], int tx, int r0) {
#pragma unroll 8
    for (int k = 0; k < 32; k++) {
        ull ap[4];
#pragma unroll
        for (int r = 0; r < 4; r++) ap[r] = pack_dup(A[(r0 + r) * AS + k]);
        const float* brow = B + k * 256 + 4 * tx;
#pragma unroll
        for (int jj = 0; jj < 4; jj++) {
            ulonglong2 bv = *reinterpret_cast<const ulonglong2*>(brow + 64 * jj);
#pragma unroll
            for (int r = 0; r < 4; r++) { fma2(acc[r][2 * jj], ap[r], bv.x); fma2(acc[r][2 * jj + 1], ap[r], bv.y); }
        }
    }
}

// ---------------- prep kernels ----------------
__global__ void zero_kernel() {
    int idx = blockIdx.x * 256 + threadIdx.x, stride = gridDim.x * 256;
    for (int i = idx; i < Nn * 256; i += stride) g_aggH[i] = 0.0f;
    for (int i = idx; i < Nn * 3; i += stride) g_aggC[i] = 0.0f;
    for (int i = idx; i < Nn; i += stride) g_cnt[i] = 0.0f;
}

// W [K=256][N=256] row-major -> fragment order per mma.m16n8k16 col-B mapping
__global__ void prep_frag(const float* __restrict__ W, int which) {
    int i = blockIdx.x * 256 + threadIdx.x;
    if (i >= 8192) return;
    int lane = i & 31, kq = (i >> 5) & 15, t = i >> 9;
    int tg = lane & 3, gq = lane >> 2;
    int k0 = kq * 16 + tg * 2;
    u32 H[4], L[4];
#pragma unroll
    for (int hf = 0; hf < 2; hf++) {
        int n = t * 16 + hf * 8 + gq;
#pragma unroll
        for (int b = 0; b < 2; b++) {
            int k = k0 + b * 8;
            float v0 = W[k * 256 + n], v1 = W[(k + 1) * 256 + n];
            __half h0 = __float2half_rn(v0), h1 = __float2half_rn(v1);
            __half l0 = __float2half_rn(v0 - __half2float(h0));
            __half l1 = __float2half_rn(v1 - __half2float(h1));
            H[hf * 2 + b] = ((u32)__half_as_ushort(h1) << 16) | __half_as_ushort(h0);
            L[hf * 2 + b] = ((u32)__half_as_ushort(l1) << 16) | __half_as_ushort(l0);
        }
    }
    uint4 vh = make_uint4(H[0], H[1], H[2], H[3]);
    uint4 vl = make_uint4(L[0], L[1], L[2], L[3]);
    if (which == 1) { g_F2h[i] = vh; g_F2l[i] = vl; }
    else            { g_Fch[i] = vh; }
}

// ---------------- P = h @ [We1_top | We1_bot]  (fp32 exact) ----------------
struct __align__(16) PSm { float B[32 * 256]; float A[64 * 33]; };
__global__ __launch_bounds__(256, 2) void pcomp_kernel(const float* __restrict__ h,
                                                       const float* __restrict__ We1) {
    extern __shared__ char smr[];
    PSm& s = *reinterpret_cast<PSm*>(smr);
    const int tid = threadIdx.x, tx = tid & 15, ty = tid >> 4, r0 = ty * 4;
    const int nb = blockIdx.x * 64, hy = blockIdx.y;
    ull acc[4][8];
#pragma unroll
    for (int r = 0; r < 4; r++)
#pragma unroll
        for (int j = 0; j < 8; j++) acc[r][j] = 0ULL;
    const int rr = tid >> 2, kk = (tid & 3) * 8;
    const int nrow = nb + rr;
    const bool vA = nrow < Nn;

    for (int kc = 0; kc < 8; kc++) {
        const int kb = kc * 32;
        float4 v0 = make_float4(0.f, 0.f, 0.f, 0.f), v1 = v0;
        if (vA) {
            const float* src = h + (size_t)nrow * 256 + kb + kk;
            v0 = *reinterpret_cast<const float4*>(src);
            v1 = *reinterpret_cast<const float4*>(src + 4);
        }
        float* da = &s.A[rr * 33 + kk];
        da[0] = v0.x; da[1] = v0.y; da[2] = v0.z; da[3] = v0.w;
        da[4] = v1.x; da[5] = v1.y; da[6] = v1.z; da[7] = v1.w;
        const float4* wsrc = reinterpret_cast<const float4*>(We1 + (size_t)(hy * 256 + kb) * 256);
        float4* wdst = reinterpret_cast<float4*>(s.B);
#pragma unroll
        for (int i = 0; i < 8; i++) wdst[tid + 256 * i] = wsrc[tid + 256 * i];
        __syncthreads();
        mma_chunk<33>(&s.A[0], s.B, acc, tx, r0);
        __syncthreads();
    }
#pragma unroll
    for (int r = 0; r < 4; r++) {
        int n = nb + r0 + r;
        if (n < Nn) {
#pragma unroll
            for (int jj = 0; jj < 4; jj++) {
                int c0 = 4 * tx + 64 * jj;
                float2 p0 = unpack2(acc[r][2 * jj]), p1 = unpack2(acc[r][2 * jj + 1]);
                *reinterpret_cast<float4*>(&g_P[(size_t)n * 512 + hy * 256 + c0]) =
                    make_float4(p0.x, p0.y, p1.x, p1.y);
            }
        }
    }
}

// ---------------- fused edge kernel (512 threads) ----------------
struct __align__(128) ESm {
    __half Xh[128 * 264];
    float w512[256], vbe1[256], vbe2[256], vbc1[256], vwc2[256];
    float rad[128], cd[384], P[256];
    int rowI[128], colI[128];
};

__global__ __launch_bounds__(512, 1) void edge_kernel(
    const float* __restrict__ coord, const int* __restrict__ ei,
    const float* __restrict__ We1, const float* __restrict__ be1,
    const float* __restrict__ be2, const float* __restrict__ bc1,
    const float* __restrict__ Wc2, const float* __restrict__ bc2) {
    extern __shared__ char smr[];
    ESm& s = *reinterpret_cast<ESm*>(smr);
    const int tid = threadIdx.x, wid = tid >> 5, lane = tid & 31;
    const int g = lane >> 2, tg = lane & 3;
    const int eb = blockIdx.x * 128;

    if (tid < 128) {
        int e = eb + tid;
        int ri = ei[e], ci = ei[Ee + e];
        s.rowI[tid] = ri; s.colI[tid] = ci;
        float dx = coord[ri * 3 + 0] - coord[ci * 3 + 0];
        float dy = coord[ri * 3 + 1] - coord[ci * 3 + 1];
        float dz = coord[ri * 3 + 2] - coord[ci * 3 + 2];
        s.cd[tid * 3 + 0] = dx; s.cd[tid * 3 + 1] = dy; s.cd[tid * 3 + 2] = dz;
        s.rad[tid] = dx * dx + dy * dy + dz * dz;
    }
    if (tid < 256) {
        s.w512[tid] = We1[512 * 256 + tid];
        s.vbe1[tid] = be1[tid];
        s.vbe2[tid] = be2[tid];
        s.vbc1[tid] = bc1[tid];
        s.vwc2[tid] = Wc2[tid];
    }
    __syncthreads();

    // ---- phase 1: X = silu(P[row] + P[col|off256] + rad*w512 + be1) ----
    {
        int e = tid >> 2, q = (tid & 3) * 64;
        const float4* pr = (const float4*)(g_P + (size_t)s.rowI[e] * 512 + q);
        const float4* pc = (const float4*)(g_P + (size_t)s.colI[e] * 512 + 256 + q);
        float radr = s.rad[e];
#pragma unroll
        for (int jj = 0; jj < 16; jj++) {
            float4 a = pr[jj], b = pc[jj];
            int c = q + jj * 4;
            float o0 = silu_fast(a.x + b.x + radr * s.w512[c + 0] + s.vbe1[c + 0]);
            float o1 = silu_fast(a.y + b.y + radr * s.w512[c + 1] + s.vbe1[c + 1]);
            float o2 = silu_fast(a.z + b.z + radr * s.w512[c + 2] + s.vbe1[c + 2]);
            float o3 = silu_fast(a.w + b.w + radr * s.w512[c + 3] + s.vbe1[c + 3]);
            *reinterpret_cast<__half2*>(&s.Xh[e * 264 + c]) =
                __halves2half2(__float2half_rn(o0), __float2half_rn(o1));
            *reinterpret_cast<__half2*>(&s.Xh[e * 264 + c + 2]) =
                __halves2half2(__float2half_rn(o2), __float2half_rn(o3));
        }
    }
    __syncthreads();

    // ---- GEMM2 (We2, 2-term) then GEMM3 (Wc1, 1-term), B direct from L2 ----
    const int mwid = wid & 7, nh = wid >> 3;
    const int aRow = (lane & 7) + (lane & 8);
    const int aK8 = (lane & 16) ? 8 : 0;
    const u32 xh_b = smem_u32(s.Xh);
    const u32 aoff = ((u32)(mwid * 16 + aRow) * 264 + aK8) * 2;
    const u32 fbase = (u32)(nh * 8 * 16) * 32 + lane;

    float d[16][4];

    // =========================== GEMM2 ===========================
    {
#pragma unroll
        for (int i = 0; i < 16; i++)
#pragma unroll
            for (int j = 0; j < 4; j++) d[i][j] = 0.0f;

        const uint4* f2h = g_F2h + fbase;
        const uint4* f2l = g_F2l + fbase;
#pragma unroll 2
        for (int kq = 0; kq < 16; kq++) {
            u32 a[4];
            ldsm4(a, xh_b + aoff + kq * 32);
#pragma unroll
            for (int ng = 0; ng < 8; ng++) {
                uint4 bh = f2h[(ng * 16 + kq) * 32];
                uint4 bl = f2l[(ng * 16 + kq) * 32];
                mma16816(d[2 * ng], a, (const u32*)&bh);
                mma16816(d[2 * ng], a, (const u32*)&bl);
                mma16816(d[2 * ng + 1], a, ((const u32*)&bh) + 2);
                mma16816(d[2 * ng + 1], a, ((const u32*)&bl) + 2);
            }
        }
        __syncthreads();  // all mma reads of Xh done before rewrite

        // epilogue 2: edge_feat = silu(D+be2); v2 atomics; rewrite Xh
        int rr1 = mwid * 16 + g, rr2 = rr1 + 8;
        int ri1 = s.rowI[rr1], ri2 = s.rowI[rr2];
#pragma unroll
        for (int ng = 0; ng < 8; ng++) {
#pragma unroll
            for (int hf = 0; hf < 2; hf++) {
                int c = nh * 128 + ng * 16 + hf * 8 + tg * 2;
                float* dd = d[2 * ng + hf];
                float o0 = silu_fast(dd[0] + s.vbe2[c]);
                float o1 = silu_fast(dd[1] + s.vbe2[c + 1]);
                float o2 = silu_fast(dd[2] + s.vbe2[c]);
                float o3 = silu_fast(dd[3] + s.vbe2[c + 1]);
                atomicAdd((float2*)&g_aggH[(size_t)ri1 * 256 + c], make_float2(o0, o1));
                atomicAdd((float2*)&g_aggH[(size_t)ri2 * 256 + c], make_float2(o2, o3));
                *reinterpret_cast<__half2*>(&s.Xh[rr1 * 264 + c]) =
                    __halves2half2(__float2half_rn(o0), __float2half_rn(o1));
                *reinterpret_cast<__half2*>(&s.Xh[rr2 * 264 + c]) =
                    __halves2half2(__float2half_rn(o2), __float2half_rn(o3));
            }
        }
    }
    __syncthreads();

    // =========================== GEMM3 (hi only) ===========================
    {
#pragma unroll
        for (int i = 0; i < 16; i++)
#pragma unroll
            for (int j = 0; j < 4; j++) d[i][j] = 0.0f;

        const uint4* fch = g_Fch + fbase;
#pragma unroll 2
        for (int kq = 0; kq < 16; kq++) {
            u32 a[4];
            ldsm4(a, xh_b + aoff + kq * 32);
#pragma unroll
            for (int ng = 0; ng < 8; ng++) {
                uint4 bh = fch[(ng * 16 + kq) * 32];
                mma16816(d[2 * ng], a, (const u32*)&bh);
                mma16816(d[2 * ng + 1], a, ((const u32*)&bh) + 2);
            }
        }

        // epilogue 3: partial dot(silu(D+bc1), wc2)
        int rr1 = mwid * 16 + g, rr2 = rr1 + 8;
        float p1 = 0.0f, p2 = 0.0f;
#pragma unroll
        for (int ng = 0; ng < 8; ng++) {
#pragma unroll
            for (int hf = 0; hf < 2; hf++) {
                int c = nh * 128 + ng * 16 + hf * 8 + tg * 2;
                float* dd = d[2 * ng + hf];
                p1 = fmaf(silu_fast(dd[0] + s.vbc1[c]), s.vwc2[c], p1);
                p1 = fmaf(silu_fast(dd[1] + s.vbc1[c + 1]), s.vwc2[c + 1], p1);
                p2 = fmaf(silu_fast(dd[2] + s.vbc1[c]), s.vwc2[c], p2);
                p2 = fmaf(silu_fast(dd[3] + s.vbc1[c + 1]), s.vwc2[c + 1], p2);
            }
        }
        p1 += __shfl_xor_sync(0xFFFFFFFF, p1, 1);
        p1 += __shfl_xor_sync(0xFFFFFFFF, p1, 2);
        p2 += __shfl_xor_sync(0xFFFFFFFF, p2, 1);
        p2 += __shfl_xor_sync(0xFFFFFFFF, p2, 2);
        if (tg == 0) {
            s.P[rr1 * 2 + nh] = p1;
            s.P[rr2 * 2 + nh] = p2;
        }
    }
    __syncthreads();

    // coord atomics
    if (tid < 128) {
        float scal = s.P[tid * 2] + s.P[tid * 2 + 1] + __ldg(bc2);
        int ri = s.rowI[tid];
        atomicAdd(&g_aggC[ri * 3 + 0], s.cd[tid * 3 + 0] * scal);
        atomicAdd(&g_aggC[ri * 3 + 1], s.cd[tid * 3 + 1] * scal);
        atomicAdd(&g_aggC[ri * 3 + 2], s.cd[tid * 3 + 2] * scal);
        atomicAdd(&g_cnt[ri], 1.0f);
    }
}

// ---------------- node kernel ----------------
struct __align__(16) NSm { float X[64 * 260]; float B[32 * 256]; float A[64 * 33]; };

__global__ __launch_bounds__(256, 2) void node_kernel(
    const float* __restrict__ h, const float* __restrict__ coord,
    const float* __restrict__ Wn1, const float* __restrict__ bn1,
    const float* __restrict__ Wn2, const float* __restrict__ bn2,
    float* __restrict__ out) {
    extern __shared__ char smem_raw[];
    NSm& s = *reinterpret_cast<NSm*>(smem_raw);
    const int tid = threadIdx.x, tx = tid & 15, ty = tid >> 4, r0 = ty * 4;
    const int nb = blockIdx.x * 64;
    ull acc[4][8];
#pragma unroll
    for (int r = 0; r < 4; r++)
#pragma unroll
        for (int j = 0; j < 8; j++) acc[r][j] = 0ULL;
    const int rr = tid >> 2, kk = (tid & 3) * 8;
    const int nrow = nb + rr;
    const bool vA = nrow < Nn;

    for (int kc = 0; kc < 16; kc++) {
        const int kb = kc * 32;
        float4 v0 = make_float4(0.f, 0.f, 0.f, 0.f), v1 = v0;
        if (vA) {
            const float* src = (kc < 8) ? h + (size_t)nrow * 256 + kb + kk
                                        : g_aggH + (size_t)nrow * 256 + (kb - 256) + kk;
            v0 = *reinterpret_cast<const float4*>(src);
            v1 = *reinterpret_cast<const float4*>(src + 4);
        }
        float* da = &s.A[rr * 33 + kk];
        da[0] = v0.x; da[1] = v0.y; da[2] = v0.z; da[3] = v0.w;
        da[4] = v1.x; da[5] = v1.y; da[6] = v1.z; da[7] = v1.w;
        const float4* wsrc = reinterpret_cast<const float4*>(Wn1 + (size_t)kb * 256);
        float4* wdst = reinterpret_cast<float4*>(s.B);
#pragma unroll
        for (int i = 0; i < 8; i++) wdst[tid + 256 * i] = wsrc[tid + 256 * i];
        __syncthreads();
        mma_chunk<33>(&s.A[0], s.B, acc, tx, r0);
        __syncthreads();
    }
#pragma unroll
    for (int r = 0; r < 4; r++)
#pragma unroll
        for (int jj = 0; jj < 4; jj++) {
            int c0 = 4 * tx + 64 * jj;
            float2 p0 = unpack2(acc[r][2 * jj]), p1 = unpack2(acc[r][2 * jj + 1]);
            float4 o;
            o.x = silu_fast(p0.x + __ldg(&bn1[c0 + 0]));
            o.y = silu_fast(p0.y + __ldg(&bn1[c0 + 1]));
            o.z = silu_fast(p1.x + __ldg(&bn1[c0 + 2]));
            o.w = silu_fast(p1.y + __ldg(&bn1[c0 + 3]));
            *reinterpret_cast<float4*>(&s.X[(r0 + r) * 260 + c0]) = o;
            acc[r][2 * jj] = 0ULL; acc[r][2 * jj + 1] = 0ULL;
        }
    __syncthreads();
    for (int kc = 0; kc < 8; kc++) {
        const int kb = kc * 32;
        const float4* wsrc = reinterpret_cast<const float4*>(Wn2 + (size_t)kb * 256);
        float4* wdst = reinterpret_cast<float4*>(s.B);
#pragma unroll
        for (int i = 0; i < 8; i++) wdst[tid + 256 * i] = wsrc[tid + 256 * i];
        __syncthreads();
        mma_chunk<260>(&s.X[kb], s.B, acc, tx, r0);
        __syncthreads();
    }
#pragma unroll
    for (int r = 0; r < 4; r++) {
        int n = nb + r0 + r;
        if (n < Nn) {
#pragma unroll
            for (int jj = 0; jj < 4; jj++) {
                int c0 = 4 * tx + 64 * jj;
                float2 p0 = unpack2(acc[r][2 * jj]), p1 = unpack2(acc[r][2 * jj + 1]);
                float4 o;
                o.x = p0.x + __ldg(&bn2[c0 + 0]); o.y = p0.y + __ldg(&bn2[c0 + 1]);
                o.z = p1.x + __ldg(&bn2[c0 + 2]); o.w = p1.y + __ldg(&bn2[c0 + 3]);
                *reinterpret_cast<float4*>(&out[(size_t)n * 256 + c0]) = o;
            }
        }
    }
    if (tid < 64) {
        int n = nb + tid;
        if (n < Nn) {
            float inv = 1.0f / fmaxf(g_cnt[n], 1.0f);
#pragma unroll
            for (int dd = 0; dd < 3; dd++)
                out[(size_t)Nn * 256 + n * 3 + dd] = coord[n * 3 + dd] + g_aggC[n * 3 + dd] * inv;
        }
    }
}

// ---------------------------------------------------------------------------
extern "C" void kernel_launch(void* const* d_in, const int* in_sizes, int n_in,
                              void* d_out, int out_size) {
    const float* h     = (const float*)d_in[0];
    const float* coord = (const float*)d_in[1];
    const int*   ei    = (const int*)d_in[2];
    const float* We1   = (const float*)d_in[3];
    const float* be1   = (const float*)d_in[4];
    const float* We2   = (const float*)d_in[5];
    const float* be2   = (const float*)d_in[6];
    const float* Wn1   = (const float*)d_in[7];
    const float* bn1   = (const float*)d_in[8];
    const float* Wn2   = (const float*)d_in[9];
    const float* bn2   = (const float*)d_in[10];
    const float* Wc1   = (const float*)d_in[11];
    const float* bc1   = (const float*)d_in[12];
    const float* Wc2   = (const float*)d_in[13];
    const float* bc2   = (const float*)d_in[14];
    float* out = (float*)d_out;

    cudaFuncSetAttribute(edge_kernel, cudaFuncAttributeMaxDynamicSharedMemorySize, (int)sizeof(ESm));
    cudaFuncSetAttribute(node_kernel, cudaFuncAttributeMaxDynamicSharedMemorySize, (int)sizeof(NSm));
    cudaFuncSetAttribute(pcomp_kernel, cudaFuncAttributeMaxDynamicSharedMemorySize, (int)sizeof(PSm));

    zero_kernel<<<1280, 256>>>();
    prep_frag<<<32, 256>>>(We2, 1);
    prep_frag<<<32, 256>>>(Wc1, 2);
    pcomp_kernel<<<dim3((Nn + 63) / 64, 2), 256, sizeof(PSm)>>>(h, We1);
    edge_kernel<<<Ee / 128, 512, sizeof(ESm)>>>(coord, ei, We1, be1, be2, bc1, Wc2, bc2);
    node_kernel<<<(Nn + 63) / 64, 256, sizeof(NSm)>>>(h, coord, Wn1, bn1, Wn2, bn2, out);
}

// round 12
// speedup vs baseline: 1.3115x; 1.3115x over previous
#include <cuda_runtime.h>
#include <cuda_fp16.h>
#include <cstdint>

#define Nn 10000
#define Ee 320000

typedef unsigned long long ull;
typedef unsigned int u32;

// ---------------- device scratch ----------------
__device__ float g_aggH[Nn * 256];
__device__ float g_aggC[Nn * 3];
__device__ float g_cnt[Nn];
__device__ __align__(16) float g_P[(size_t)Nn * 512];
__device__ __align__(16) __half g_W2h[256 * 256];
__device__ __align__(16) __half g_W2l[256 * 256];
__device__ __align__(16) __half g_Wch[256 * 256];

// ---------------- helpers ----------------
__device__ __forceinline__ u32 smem_u32(const void* p) {
    u32 a;
    asm("{ .reg .u64 t; cvta.to.shared.u64 t, %1; cvt.u32.u64 %0, t; }" : "=r"(a) : "l"(p));
    return a;
}
__device__ __forceinline__ void ldsm4(u32* r, u32 addr) {
    asm volatile("ldmatrix.sync.aligned.m8n8.x4.shared.b16 {%0,%1,%2,%3},[%4];"
                 : "=r"(r[0]), "=r"(r[1]), "=r"(r[2]), "=r"(r[3]) : "r"(addr));
}
__device__ __forceinline__ void mma16816(float* d, const u32* a, const u32* b) {
    asm volatile(
        "mma.sync.aligned.m16n8k16.row.col.f32.f16.f16.f32 "
        "{%0,%1,%2,%3},{%4,%5,%6,%7},{%8,%9},{%0,%1,%2,%3};"
        : "+f"(d[0]), "+f"(d[1]), "+f"(d[2]), "+f"(d[3])
        : "r"(a[0]), "r"(a[1]), "r"(a[2]), "r"(a[3]), "r"(b[0]), "r"(b[1]));
}

// MUFU-free silu
__device__ __forceinline__ float silu_fast(float x) {
    float v = fmaxf(-fabsf(x) * 1.4426950408889634f, -30.0f);
    float r = v + 12582912.0f;
    int ni = __float_as_int(r) - 0x4B400000;
    float f = v - (r - 12582912.0f);
    float p = 1.3333558146e-3f;
    p = fmaf(p, f, 9.6181291076e-3f);
    p = fmaf(p, f, 5.5504108664e-2f);
    p = fmaf(p, f, 2.4015967802e-1f);
    p = fmaf(p, f, 6.9314718056e-1f);
    p = fmaf(p, f, 1.0f);
    float z = __int_as_float(__float_as_int(p) + (ni << 23));
    float d = 1.0f + z;
    float y = __int_as_float(0x7EF311C3 - __float_as_int(d));
    y = y * fmaf(-d, y, 2.0f);
    y = y * fmaf(-d, y, 2.0f);
    y = y * fmaf(-d, y, 2.0f);
    float sig = (x >= 0.0f) ? y : (1.0f - y);
    return x * sig;
}

// ---------------- fp32 FFMA2 GEMM pieces ----------------
__device__ __forceinline__ ull pack_dup(float a) { ull r; asm("mov.b64 %0,{%1,%1};" : "=l"(r) : "f"(a)); return r; }
__device__ __forceinline__ float2 unpack2(ull v) { float2 r; asm("mov.b64 {%0,%1},%2;" : "=f"(r.x), "=f"(r.y) : "l"(v)); return r; }
__device__ __forceinline__ void fma2(ull& d, ull a, ull b) { asm("fma.rn.f32x2 %0,%1,%2,%0;" : "+l"(d) : "l"(a), "l"(b)); }

template <int AS>
__device__ __forceinline__ void mma_chunk(const float* __restrict__ A, const float* __restrict__ B,
                                          ull acc[4][8], int tx, int r0) {
#pragma unroll 8
    for (int k = 0; k < 32; k++) {
        ull ap[4];
#pragma unroll
        for (int r = 0; r < 4; r++) ap[r] = pack_dup(A[(r0 + r) * AS + k]);
        const float* brow = B + k * 256 + 4 * tx;
#pragma unroll
        for (int jj = 0; jj < 4; jj++) {
            ulonglong2 bv = *reinterpret_cast<const ulonglong2*>(brow + 64 * jj);
#pragma unroll
            for (int r = 0; r < 4; r++) { fma2(acc[r][2 * jj], ap[r], bv.x); fma2(acc[r][2 * jj + 1], ap[r], bv.y); }
        }
    }
}

// ---------------- prep kernels ----------------
__global__ void zero_kernel() {
    int idx = blockIdx.x * 256 + threadIdx.x, stride = gridDim.x * 256;
    for (int i = idx; i < Nn * 256; i += stride) g_aggH[i] = 0.0f;
    for (int i = idx; i < Nn * 3; i += stride) g_aggC[i] = 0.0f;
    for (int i = idx; i < Nn; i += stride) g_cnt[i] = 0.0f;
}
__global__ void prep_w(const float* __restrict__ W, int which) {
    int i = blockIdx.x * 256 + threadIdx.x;
    if (i >= 256 * 256) return;
    int k = i >> 8, n = i & 255;
    float v = W[i];
    __half hb = __float2half_rn(v);
    if (which == 1) {
        g_W2h[(size_t)n * 256 + k] = hb;
        g_W2l[(size_t)n * 256 + k] = __float2half_rn(v - __half2float(hb));
    } else {
        g_Wch[(size_t)n * 256 + k] = hb;
    }
}

// ---------------- P = h @ [We1_top | We1_bot]  (fp32 exact) ----------------
struct __align__(16) PSm { float B[32 * 256]; float A[64 * 33]; };
__global__ __launch_bounds__(256, 2) void pcomp_kernel(const float* __restrict__ h,
                                                       const float* __restrict__ We1) {
    extern __shared__ char smr[];
    PSm& s = *reinterpret_cast<PSm*>(smr);
    const int tid = threadIdx.x, tx = tid & 15, ty = tid >> 4, r0 = ty * 4;
    const int nb = blockIdx.x * 64, hy = blockIdx.y;
    ull acc[4][8];
#pragma unroll
    for (int r = 0; r < 4; r++)
#pragma unroll
        for (int j = 0; j < 8; j++) acc[r][j] = 0ULL;
    const int rr = tid >> 2, kk = (tid & 3) * 8;
    const int nrow = nb + rr;
    const bool vA = nrow < Nn;

    for (int kc = 0; kc < 8; kc++) {
        const int kb = kc * 32;
        float4 v0 = make_float4(0.f, 0.f, 0.f, 0.f), v1 = v0;
        if (vA) {
            const float* src = h + (size_t)nrow * 256 + kb + kk;
            v0 = *reinterpret_cast<const float4*>(src);
            v1 = *reinterpret_cast<const float4*>(src + 4);
        }
        float* da = &s.A[rr * 33 + kk];
        da[0] = v0.x; da[1] = v0.y; da[2] = v0.z; da[3] = v0.w;
        da[4] = v1.x; da[5] = v1.y; da[6] = v1.z; da[7] = v1.w;
        const float4* wsrc = reinterpret_cast<const float4*>(We1 + (size_t)(hy * 256 + kb) * 256);
        float4* wdst = reinterpret_cast<float4*>(s.B);
#pragma unroll
        for (int i = 0; i < 8; i++) wdst[tid + 256 * i] = wsrc[tid + 256 * i];
        __syncthreads();
        mma_chunk<33>(&s.A[0], s.B, acc, tx, r0);
        __syncthreads();
    }
#pragma unroll
    for (int r = 0; r < 4; r++) {
        int n = nb + r0 + r;
        if (n < Nn) {
#pragma unroll
            for (int jj = 0; jj < 4; jj++) {
                int c0 = 4 * tx + 64 * jj;
                float2 p0 = unpack2(acc[r][2 * jj]), p1 = unpack2(acc[r][2 * jj + 1]);
                *reinterpret_cast<float4*>(&g_P[(size_t)n * 512 + hy * 256 + c0]) =
                    make_float4(p0.x, p0.y, p1.x, p1.y);
            }
        }
    }
}

// ---------------- fused edge kernel (512 threads) ----------------
struct __align__(128) ESm {
    __half Xh[128 * 264];       // fp16 activations (hi only)
    __half BH[2][256 * 40];     // double-buffered weight hi
    __half BL[2][256 * 40];     // double-buffered weight lo (GEMM2 only)
    float w512[256], vbe1[256], vbe2[256], vbc1[256], vwc2[256];
    float rad[128], cd[384], P[256];
    int rowI[128], colI[128];
};

__global__ __launch_bounds__(512, 1) void edge_kernel(
    const float* __restrict__ coord, const int* __restrict__ ei,
    const float* __restrict__ We1, const float* __restrict__ be1,
    const float* __restrict__ be2, const float* __restrict__ bc1,
    const float* __restrict__ Wc2, const float* __restrict__ bc2) {
    extern __shared__ char smr[];
    ESm& s = *reinterpret_cast<ESm*>(smr);
    const int tid = threadIdx.x, wid = tid >> 5, lane = tid & 31;
    const int g = lane >> 2, tg = lane & 3;
    const int eb = blockIdx.x * 128;

    if (tid < 128) {
        int e = eb + tid;
        int ri = ei[e], ci = ei[Ee + e];
        s.rowI[tid] = ri; s.colI[tid] = ci;
        float dx = coord[ri * 3 + 0] - coord[ci * 3 + 0];
        float dy = coord[ri * 3 + 1] - coord[ci * 3 + 1];
        float dz = coord[ri * 3 + 2] - coord[ci * 3 + 2];
        s.cd[tid * 3 + 0] = dx; s.cd[tid * 3 + 1] = dy; s.cd[tid * 3 + 2] = dz;
        s.rad[tid] = dx * dx + dy * dy + dz * dz;
    }
    if (tid < 256) {
        s.w512[tid] = We1[512 * 256 + tid];
        s.vbe1[tid] = be1[tid];
        s.vbe2[tid] = be2[tid];
        s.vbc1[tid] = bc1[tid];
        s.vwc2[tid] = Wc2[tid];
    }
    __syncthreads();

    // ---- phase 1: X = silu(P[row] + P[col|off256] + rad*w512 + be1) ----
    {
        int e = tid >> 2, q = (tid & 3) * 64;
        const float4* pr = (const float4*)(g_P + (size_t)s.rowI[e] * 512 + q);
        const float4* pc = (const float4*)(g_P + (size_t)s.colI[e] * 512 + 256 + q);
        float radr = s.rad[e];
#pragma unroll
        for (int jj = 0; jj < 16; jj++) {
            float4 a = pr[jj], b = pc[jj];
            int c = q + jj * 4;
            float o0 = silu_fast(a.x + b.x + radr * s.w512[c + 0] + s.vbe1[c + 0]);
            float o1 = silu_fast(a.y + b.y + radr * s.w512[c + 1] + s.vbe1[c + 1]);
            float o2 = silu_fast(a.z + b.z + radr * s.w512[c + 2] + s.vbe1[c + 2]);
            float o3 = silu_fast(a.w + b.w + radr * s.w512[c + 3] + s.vbe1[c + 3]);
            *reinterpret_cast<__half2*>(&s.Xh[e * 264 + c]) =
                __halves2half2(__float2half_rn(o0), __float2half_rn(o1));
            *reinterpret_cast<__half2*>(&s.Xh[e * 264 + c + 2]) =
                __halves2half2(__float2half_rn(o2), __float2half_rn(o3));
        }
    }
    __syncthreads();

    // ---- GEMM2 (We2, 2-term) then GEMM3 (Wc1, 1-term) ----
    const int mwid = wid & 7, nh = wid >> 3;
    const int aRow = (lane & 7) + (lane & 8);
    const int aK8 = (lane & 16) ? 8 : 0;
    const int bRow = (lane & 7) + ((lane & 16) ? 8 : 0);
    const int bK8 = (lane & 8) ? 8 : 0;
    const u32 xh_b = smem_u32(s.Xh);
    const u32 aoff = ((u32)(mwid * 16 + aRow) * 264 + aK8) * 2;
    const u32 boffL = ((u32)(nh * 128 + bRow) * 40 + bK8) * 2;
    const u32 bh_b0 = smem_u32(s.BH[0]) + boffL, bh_b1 = smem_u32(s.BH[1]) + boffL;
    const u32 bl_b0 = smem_u32(s.BL[0]) + boffL, bl_b1 = smem_u32(s.BL[1]) + boffL;
    const int sn = tid >> 1, sh = tid & 1;

    float d[16][4];

    // =========================== GEMM2 ===========================
    {
#pragma unroll
        for (int i = 0; i < 16; i++)
#pragma unroll
            for (int j = 0; j < 4; j++) d[i][j] = 0.0f;

        uint4 pbh[2], pbl[2];
        auto loadB = [&](int kc) {
            const uint4* bh4 = (const uint4*)(g_W2h + (size_t)sn * 256 + kc * 32 + sh * 16);
            const uint4* bl4 = (const uint4*)(g_W2l + (size_t)sn * 256 + kc * 32 + sh * 16);
            pbh[0] = bh4[0]; pbh[1] = bh4[1];
            pbl[0] = bl4[0]; pbl[1] = bl4[1];
        };
        auto storeB = [&](int b) {
            *(uint4*)&s.BH[b][sn * 40 + sh * 16] = pbh[0];
            *(uint4*)&s.BH[b][sn * 40 + sh * 16 + 8] = pbh[1];
            *(uint4*)&s.BL[b][sn * 40 + sh * 16] = pbl[0];
            *(uint4*)&s.BL[b][sn * 40 + sh * 16 + 8] = pbl[1];
        };
        loadB(0); storeB(0);
        __syncthreads();

        for (int kc = 0; kc < 8; kc++) {
            if (kc < 7) loadB(kc + 1);
            const u32 bhc = (kc & 1) ? bh_b1 : bh_b0;
            const u32 blc = (kc & 1) ? bl_b1 : bl_b0;
#pragma unroll
            for (int ks = 0; ks < 2; ks++) {
                u32 ah[4];
                ldsm4(ah, xh_b + aoff + (kc * 32 + ks * 16) * 2);
#pragma unroll
                for (int ng = 0; ng < 8; ng++) {
                    u32 bh[4], bl[4];
                    ldsm4(bh, bhc + ng * 1280 + ks * 32);
                    ldsm4(bl, blc + ng * 1280 + ks * 32);
                    mma16816(d[2 * ng], ah, bh);
                    mma16816(d[2 * ng], ah, bl);
                    mma16816(d[2 * ng + 1], ah, bh + 2);
                    mma16816(d[2 * ng + 1], ah, bl + 2);
                }
            }
            if (kc < 7) storeB((kc + 1) & 1);
            __syncthreads();
        }

        // epilogue 2: edge_feat = silu(D+be2) -> Xh only (no atomics here)
        int rr1 = mwid * 16 + g, rr2 = rr1 + 8;
#pragma unroll
        for (int ng = 0; ng < 8; ng++) {
#pragma unroll
            for (int hf = 0; hf < 2; hf++) {
                int c = nh * 128 + ng * 16 + hf * 8 + tg * 2;
                float* dd = d[2 * ng + hf];
                float o0 = silu_fast(dd[0] + s.vbe2[c]);
                float o1 = silu_fast(dd[1] + s.vbe2[c + 1]);
                float o2 = silu_fast(dd[2] + s.vbe2[c]);
                float o3 = silu_fast(dd[3] + s.vbe2[c + 1]);
                *reinterpret_cast<__half2*>(&s.Xh[rr1 * 264 + c]) =
                    __halves2half2(__float2half_rn(o0), __float2half_rn(o1));
                *reinterpret_cast<__half2*>(&s.Xh[rr2 * 264 + c]) =
                    __halves2half2(__float2half_rn(o2), __float2half_rn(o3));
            }
        }
    }
    __syncthreads();

    // ---- aggregation pass: coalesced float4 atomics from Xh ----
    {
        int r = tid >> 2, q = (tid & 3) * 64;
        int ri = s.rowI[r];
        const __half2* xr = (const __half2*)&s.Xh[r * 264 + q];
        float* dst = &g_aggH[(size_t)ri * 256 + q];
#pragma unroll
        for (int j = 0; j < 16; j++) {
            float2 a = __half22float2(xr[2 * j]);
            float2 b = __half22float2(xr[2 * j + 1]);
            atomicAdd((float4*)&dst[j * 4], make_float4(a.x, a.y, b.x, b.y));
        }
    }

    // =========================== GEMM3 (hi only) ===========================
    {
#pragma unroll
        for (int i = 0; i < 16; i++)
#pragma unroll
            for (int j = 0; j < 4; j++) d[i][j] = 0.0f;

        uint4 pbh[2];
        auto loadB = [&](int kc) {
            const uint4* bh4 = (const uint4*)(g_Wch + (size_t)sn * 256 + kc * 32 + sh * 16);
            pbh[0] = bh4[0]; pbh[1] = bh4[1];
        };
        auto storeB = [&](int b) {
            *(uint4*)&s.BH[b][sn * 40 + sh * 16] = pbh[0];
            *(uint4*)&s.BH[b][sn * 40 + sh * 16 + 8] = pbh[1];
        };
        loadB(0); storeB(0);
        __syncthreads();

        for (int kc = 0; kc < 8; kc++) {
            if (kc < 7) loadB(kc + 1);
            const u32 bhc = (kc & 1) ? bh_b1 : bh_b0;
#pragma unroll
            for (int ks = 0; ks < 2; ks++) {
                u32 ah[4];
                ldsm4(ah, xh_b + aoff + (kc * 32 + ks * 16) * 2);
#pragma unroll
                for (int ng = 0; ng < 8; ng++) {
                    u32 bh[4];
                    ldsm4(bh, bhc + ng * 1280 + ks * 32);
                    mma16816(d[2 * ng], ah, bh);
                    mma16816(d[2 * ng + 1], ah, bh + 2);
                }
            }
            if (kc < 7) storeB((kc + 1) & 1);
            __syncthreads();
        }

        // epilogue 3: partial dot(silu(D+bc1), wc2)
        int rr1 = mwid * 16 + g, rr2 = rr1 + 8;
        float p1 = 0.0f, p2 = 0.0f;
#pragma unroll
        for (int ng = 0; ng < 8; ng++) {
#pragma unroll
            for (int hf = 0; hf < 2; hf++) {
                int c = nh * 128 + ng * 16 + hf * 8 + tg * 2;
                float* dd = d[2 * ng + hf];
                p1 = fmaf(silu_fast(dd[0] + s.vbc1[c]), s.vwc2[c], p1);
                p1 = fmaf(silu_fast(dd[1] + s.vbc1[c + 1]), s.vwc2[c + 1], p1);
                p2 = fmaf(silu_fast(dd[2] + s.vbc1[c]), s.vwc2[c], p2);
                p2 = fmaf(silu_fast(dd[3] + s.vbc1[c + 1]), s.vwc2[c + 1], p2);
            }
        }
        p1 += __shfl_xor_sync(0xFFFFFFFF, p1, 1);
        p1 += __shfl_xor_sync(0xFFFFFFFF, p1, 2);
        p2 += __shfl_xor_sync(0xFFFFFFFF, p2, 1);
        p2 += __shfl_xor_sync(0xFFFFFFFF, p2, 2);
        if (tg == 0) {
            s.P[rr1 * 2 + nh] = p1;
            s.P[rr2 * 2 + nh] = p2;
        }
    }
    __syncthreads();

    // coord atomics
    if (tid < 128) {
        float scal = s.P[tid * 2] + s.P[tid * 2 + 1] + __ldg(bc2);
        int ri = s.rowI[tid];
        atomicAdd(&g_aggC[ri * 3 + 0], s.cd[tid * 3 + 0] * scal);
        atomicAdd(&g_aggC[ri * 3 + 1], s.cd[tid * 3 + 1] * scal);
        atomicAdd(&g_aggC[ri * 3 + 2], s.cd[tid * 3 + 2] * scal);
        atomicAdd(&g_cnt[ri], 1.0f);
    }
}

// ---------------- node kernel ----------------
struct __align__(16) NSm { float X[64 * 260]; float B[32 * 256]; float A[64 * 33]; };

__global__ __launch_bounds__(256, 2) void node_kernel(
    const float* __restrict__ h, const float* __restrict__ coord,
    const float* __restrict__ Wn1, const float* __restrict__ bn1,
    const float* __restrict__ Wn2, const float* __restrict__ bn2,
    float* __restrict__ out) {
    extern __shared__ char smem_raw[];
    NSm& s = *reinterpret_cast<NSm*>(smem_raw);
    const int tid = threadIdx.x, tx = tid & 15, ty = tid >> 4, r0 = ty * 4;
    const int nb = blockIdx.x * 64;
    ull acc[4][8];
#pragma unroll
    for (int r = 0; r < 4; r++)
#pragma unroll
        for (int j = 0; j < 8; j++) acc[r][j] = 0ULL;
    const int rr = tid >> 2, kk = (tid & 3) * 8;
    const int nrow = nb + rr;
    const bool vA = nrow < Nn;

    for (int kc = 0; kc < 16; kc++) {
        const int kb = kc * 32;
        float4 v0 = make_float4(0.f, 0.f, 0.f, 0.f), v1 = v0;
        if (vA) {
            const float* src = (kc < 8) ? h + (size_t)nrow * 256 + kb + kk
                                        : g_aggH + (size_t)nrow * 256 + (kb - 256) + kk;
            v0 = *reinterpret_cast<const float4*>(src);
            v1 = *reinterpret_cast<const float4*>(src + 4);
        }
        float* da = &s.A[rr * 33 + kk];
        da[0] = v0.x; da[1] = v0.y; da[2] = v0.z; da[3] = v0.w;
        da[4] = v1.x; da[5] = v1.y; da[6] = v1.z; da[7] = v1.w;
        const float4* wsrc = reinterpret_cast<const float4*>(Wn1 + (size_t)kb * 256);
        float4* wdst = reinterpret_cast<float4*>(s.B);
#pragma unroll
        for (int i = 0; i < 8; i++) wdst[tid + 256 * i] = wsrc[tid + 256 * i];
        __syncthreads();
        mma_chunk<33>(&s.A[0], s.B, acc, tx, r0);
        __syncthreads();
    }
#pragma unroll
    for (int r = 0; r < 4; r++)
#pragma unroll
        for (int jj = 0; jj < 4; jj++) {
            int c0 = 4 * tx + 64 * jj;
            float2 p0 = unpack2(acc[r][2 * jj]), p1 = unpack2(acc[r][2 * jj + 1]);
            float4 o;
            o.x = silu_fast(p0.x + __ldg(&bn1[c0 + 0]));
            o.y = silu_fast(p0.y + __ldg(&bn1[c0 + 1]));
            o.z = silu_fast(p1.x + __ldg(&bn1[c0 + 2]));
            o.w = silu_fast(p1.y + __ldg(&bn1[c0 + 3]));
            *reinterpret_cast<float4*>(&s.X[(r0 + r) * 260 + c0]) = o;
            acc[r][2 * jj] = 0ULL; acc[r][2 * jj + 1] = 0ULL;
        }
    __syncthreads();
    for (int kc = 0; kc < 8; kc++) {
        const int kb = kc * 32;
        const float4* wsrc = reinterpret_cast<const float4*>(Wn2 + (size_t)kb * 256);
        float4* wdst = reinterpret_cast<float4*>(s.B);
#pragma unroll
        for (int i = 0; i < 8; i++) wdst[tid + 256 * i] = wsrc[tid + 256 * i];
        __syncthreads();
        mma_chunk<260>(&s.X[kb], s.B, acc, tx, r0);
        __syncthreads();
    }
#pragma unroll
    for (int r = 0; r < 4; r++) {
        int n = nb + r0 + r;
        if (n < Nn) {
#pragma unroll
            for (int jj = 0; jj < 4; jj++) {
                int c0 = 4 * tx + 64 * jj;
                float2 p0 = unpack2(acc[r][2 * jj]), p1 = unpack2(acc[r][2 * jj + 1]);
                float4 o;
                o.x = p0.x + __ldg(&bn2[c0 + 0]); o.y = p0.y + __ldg(&bn2[c0 + 1]);
                o.z = p1.x + __ldg(&bn2[c0 + 2]); o.w = p1.y + __ldg(&bn2[c0 + 3]);
                *reinterpret_cast<float4*>(&out[(size_t)n * 256 + c0]) = o;
            }
        }
    }
    if (tid < 64) {
        int n = nb + tid;
        if (n < Nn) {
            float inv = 1.0f / fmaxf(g_cnt[n], 1.0f);
#pragma unroll
            for (int dd = 0; dd < 3; dd++)
                out[(size_t)Nn * 256 + n * 3 + dd] = coord[n * 3 + dd] + g_aggC[n * 3 + dd] * inv;
        }
    }
}

// ---------------------------------------------------------------------------
extern "C" void kernel_launch(void* const* d_in, const int* in_sizes, int n_in,
                              void* d_out, int out_size) {
    const float* h     = (const float*)d_in[0];
    const float* coord = (const float*)d_in[1];
    const int*   ei    = (const int*)d_in[2];
    const float* We1   = (const float*)d_in[3];
    const float* be1   = (const float*)d_in[4];
    const float* We2   = (const float*)d_in[5];
    const float* be2   = (const float*)d_in[6];
    const float* Wn1   = (const float*)d_in[7];
    const float* bn1   = (const float*)d_in[8];
    const float* Wn2   = (const float*)d_in[9];
    const float* bn2   = (const float*)d_in[10];
    const float* Wc1   = (const float*)d_in[11];
    const float* bc1   = (const float*)d_in[12];
    const float* Wc2   = (const float*)d_in[13];
    const float* bc2   = (const float*)d_in[14];
    float* out = (float*)d_out;

    cudaFuncSetAttribute(edge_kernel, cudaFuncAttributeMaxDynamicSharedMemorySize, (int)sizeof(ESm));
    cudaFuncSetAttribute(node_kernel, cudaFuncAttributeMaxDynamicSharedMemorySize, (int)sizeof(NSm));
    cudaFuncSetAttribute(pcomp_kernel, cudaFuncAttributeMaxDynamicSharedMemorySize, (int)sizeof(PSm));

    zero_kernel<<<1280, 256>>>();
    prep_w<<<256, 256>>>(We2, 1);
    prep_w<<<256, 256>>>(Wc1, 2);
    pcomp_kernel<<<dim3((Nn + 63) / 64, 2), 256, sizeof(PSm)>>>(h, We1);
    edge_kernel<<<Ee / 128, 512, sizeof(ESm)>>>(coord, ei, We1, be1, be2, bc1, Wc2, bc2);
    node_kernel<<<(Nn + 63) / 64, 256, sizeof(NSm)>>>(h, coord, Wn1, bn1, Wn2, bn2, out);
}

// round 13
// speedup vs baseline: 1.3988x; 1.0666x over previous
#include <cuda_runtime.h>
#include <cuda_fp16.h>
#include <cstdint>

#define Nn 10000
#define Ee 320000

typedef unsigned long long ull;
typedef unsigned int u32;

// ---------------- device scratch ----------------
__device__ float g_aggH[Nn * 256];
__device__ float g_aggC[Nn * 3];
__device__ float g_cnt[Nn];
__device__ __align__(16) float g_P[(size_t)Nn * 512];
__device__ __align__(16) __half g_W2h[256 * 256];
__device__ __align__(16) __half g_Wch[256 * 256];

// ---------------- helpers ----------------
__device__ __forceinline__ u32 smem_u32(const void* p) {
    u32 a;
    asm("{ .reg .u64 t; cvta.to.shared.u64 t, %1; cvt.u32.u64 %0, t; }" : "=r"(a) : "l"(p));
    return a;
}
__device__ __forceinline__ void ldsm4(u32* r, u32 addr) {
    asm volatile("ldmatrix.sync.aligned.m8n8.x4.shared.b16 {%0,%1,%2,%3},[%4];"
                 : "=r"(r[0]), "=r"(r[1]), "=r"(r[2]), "=r"(r[3]) : "r"(addr));
}
__device__ __forceinline__ void mma16816(float* d, const u32* a, const u32* b) {
    asm volatile(
        "mma.sync.aligned.m16n8k16.row.col.f32.f16.f16.f32 "
        "{%0,%1,%2,%3},{%4,%5,%6,%7},{%8,%9},{%0,%1,%2,%3};"
        : "+f"(d[0]), "+f"(d[1]), "+f"(d[2]), "+f"(d[3])
        : "r"(a[0]), "r"(a[1]), "r"(a[2]), "r"(a[3]), "r"(b[0]), "r"(b[1]));
}

// MUFU-free silu
__device__ __forceinline__ float silu_fast(float x) {
    float v = fmaxf(-fabsf(x) * 1.4426950408889634f, -30.0f);
    float r = v + 12582912.0f;
    int ni = __float_as_int(r) - 0x4B400000;
    float f = v - (r - 12582912.0f);
    float p = 1.3333558146e-3f;
    p = fmaf(p, f, 9.6181291076e-3f);
    p = fmaf(p, f, 5.5504108664e-2f);
    p = fmaf(p, f, 2.4015967802e-1f);
    p = fmaf(p, f, 6.9314718056e-1f);
    p = fmaf(p, f, 1.0f);
    float z = __int_as_float(__float_as_int(p) + (ni << 23));
    float d = 1.0f + z;
    float y = __int_as_float(0x7EF311C3 - __float_as_int(d));
    y = y * fmaf(-d, y, 2.0f);
    y = y * fmaf(-d, y, 2.0f);
    y = y * fmaf(-d, y, 2.0f);
    float sig = (x >= 0.0f) ? y : (1.0f - y);
    return x * sig;
}

// ---------------- fp32 FFMA2 GEMM pieces ----------------
__device__ __forceinline__ ull pack_dup(float a) { ull r; asm("mov.b64 %0,{%1,%1};" : "=l"(r) : "f"(a)); return r; }
__device__ __forceinline__ float2 unpack2(ull v) { float2 r; asm("mov.b64 {%0,%1},%2;" : "=f"(r.x), "=f"(r.y) : "l"(v)); return r; }
__device__ __forceinline__ void fma2(ull& d, ull a, ull b) { asm("fma.rn.f32x2 %0,%1,%2,%0;" : "+l"(d) : "l"(a), "l"(b)); }

template <int AS>
__device__ __forceinline__ void mma_chunk(const float* __restrict__ A, const float* __restrict__ B,
                                          ull acc[4][8], int tx, int r0) {
#pragma unroll 8
    for (int k = 0; k < 32; k++) {
        ull ap[4];
#pragma unroll
        for (int r = 0; r < 4; r++) ap[r] = pack_dup(A[(r0 + r) * AS + k]);
        const float* brow = B + k * 256 + 4 * tx;
#pragma unroll
        for (int jj = 0; jj < 4; jj++) {
            ulonglong2 bv = *reinterpret_cast<const ulonglong2*>(brow + 64 * jj);
#pragma unroll
            for (int r = 0; r < 4; r++) { fma2(acc[r][2 * jj], ap[r], bv.x); fma2(acc[r][2 * jj + 1], ap[r], bv.y); }
        }
    }
}

// ---------------- prep kernels ----------------
__global__ void zero_kernel() {
    int idx = blockIdx.x * 256 + threadIdx.x, stride = gridDim.x * 256;
    for (int i = idx; i < Nn * 256; i += stride) g_aggH[i] = 0.0f;
    for (int i = idx; i < Nn * 3; i += stride) g_aggC[i] = 0.0f;
    for (int i = idx; i < Nn; i += stride) g_cnt[i] = 0.0f;
}
// W [K=256][N=256] row-major -> W^T hi [256][256]
__global__ void prep_w(const float* __restrict__ W, int which) {
    int i = blockIdx.x * 256 + threadIdx.x;
    if (i >= 256 * 256) return;
    int k = i >> 8, n = i & 255;
    __half hb = __float2half_rn(W[i]);
    if (which == 1) g_W2h[(size_t)n * 256 + k] = hb;
    else            g_Wch[(size_t)n * 256 + k] = hb;
}

// ---------------- P = h @ [We1_top | We1_bot]  (fp32 exact) ----------------
struct __align__(16) PSm { float B[32 * 256]; float A[64 * 33]; };
__global__ __launch_bounds__(256, 2) void pcomp_kernel(const float* __restrict__ h,
                                                       const float* __restrict__ We1) {
    extern __shared__ char smr[];
    PSm& s = *reinterpret_cast<PSm*>(smr);
    const int tid = threadIdx.x, tx = tid & 15, ty = tid >> 4, r0 = ty * 4;
    const int nb = blockIdx.x * 64, hy = blockIdx.y;
    ull acc[4][8];
#pragma unroll
    for (int r = 0; r < 4; r++)
#pragma unroll
        for (int j = 0; j < 8; j++) acc[r][j] = 0ULL;
    const int rr = tid >> 2, kk = (tid & 3) * 8;
    const int nrow = nb + rr;
    const bool vA = nrow < Nn;

    for (int kc = 0; kc < 8; kc++) {
        const int kb = kc * 32;
        float4 v0 = make_float4(0.f, 0.f, 0.f, 0.f), v1 = v0;
        if (vA) {
            const float* src = h + (size_t)nrow * 256 + kb + kk;
            v0 = *reinterpret_cast<const float4*>(src);
            v1 = *reinterpret_cast<const float4*>(src + 4);
        }
        float* da = &s.A[rr * 33 + kk];
        da[0] = v0.x; da[1] = v0.y; da[2] = v0.z; da[3] = v0.w;
        da[4] = v1.x; da[5] = v1.y; da[6] = v1.z; da[7] = v1.w;
        const float4* wsrc = reinterpret_cast<const float4*>(We1 + (size_t)(hy * 256 + kb) * 256);
        float4* wdst = reinterpret_cast<float4*>(s.B);
#pragma unroll
        for (int i = 0; i < 8; i++) wdst[tid + 256 * i] = wsrc[tid + 256 * i];
        __syncthreads();
        mma_chunk<33>(&s.A[0], s.B, acc, tx, r0);
        __syncthreads();
    }
#pragma unroll
    for (int r = 0; r < 4; r++) {
        int n = nb + r0 + r;
        if (n < Nn) {
#pragma unroll
            for (int jj = 0; jj < 4; jj++) {
                int c0 = 4 * tx + 64 * jj;
                float2 p0 = unpack2(acc[r][2 * jj]), p1 = unpack2(acc[r][2 * jj + 1]);
                *reinterpret_cast<float4*>(&g_P[(size_t)n * 512 + hy * 256 + c0]) =
                    make_float4(p0.x, p0.y, p1.x, p1.y);
            }
        }
    }
}

// ---------------- fused edge kernel: 64 edges, 512 threads, occupancy 2 ----------------
struct __align__(128) ESm {
    __half Xh[64 * 264];        // 33792 B
    __half BH[2][256 * 24];     // 24576 B, double-buffered 16-wide K chunks
    float w512[256], vbe1[256], vbe2[256], vbc1[256], vwc2[256];
    float rad[64], cd[192], P[256];
    int rowI[64], colI[64];
};

__global__ __launch_bounds__(512, 2) void edge_kernel(
    const float* __restrict__ coord, const int* __restrict__ ei,
    const float* __restrict__ We1, const float* __restrict__ be1,
    const float* __restrict__ be2, const float* __restrict__ bc1,
    const float* __restrict__ Wc2, const float* __restrict__ bc2) {
    extern __shared__ char smr[];
    ESm& s = *reinterpret_cast<ESm*>(smr);
    const int tid = threadIdx.x, wid = tid >> 5, lane = tid & 31;
    const int g = lane >> 2, tg = lane & 3;
    const int eb = blockIdx.x * 64;

    if (tid < 64) {
        int e = eb + tid;
        int ri = ei[e], ci = ei[Ee + e];
        s.rowI[tid] = ri; s.colI[tid] = ci;
        float dx = coord[ri * 3 + 0] - coord[ci * 3 + 0];
        float dy = coord[ri * 3 + 1] - coord[ci * 3 + 1];
        float dz = coord[ri * 3 + 2] - coord[ci * 3 + 2];
        s.cd[tid * 3 + 0] = dx; s.cd[tid * 3 + 1] = dy; s.cd[tid * 3 + 2] = dz;
        s.rad[tid] = dx * dx + dy * dy + dz * dz;
    }
    if (tid < 256) {
        s.w512[tid] = We1[512 * 256 + tid];
        s.vbe1[tid] = be1[tid];
        s.vbe2[tid] = be2[tid];
        s.vbc1[tid] = bc1[tid];
        s.vwc2[tid] = Wc2[tid];
    }
    __syncthreads();

    // ---- phase 1: X = silu(P[row] + P[col|off256] + rad*w512 + be1), fp16 ----
    {
        int e = tid >> 3, q = (tid & 7) * 32;
        const float4* pr = (const float4*)(g_P + (size_t)s.rowI[e] * 512 + q);
        const float4* pc = (const float4*)(g_P + (size_t)s.colI[e] * 512 + 256 + q);
        float radr = s.rad[e];
#pragma unroll
        for (int jj = 0; jj < 8; jj++) {
            float4 a = pr[jj], b = pc[jj];
            int c = q + jj * 4;
            float o0 = silu_fast(a.x + b.x + radr * s.w512[c + 0] + s.vbe1[c + 0]);
            float o1 = silu_fast(a.y + b.y + radr * s.w512[c + 1] + s.vbe1[c + 1]);
            float o2 = silu_fast(a.z + b.z + radr * s.w512[c + 2] + s.vbe1[c + 2]);
            float o3 = silu_fast(a.w + b.w + radr * s.w512[c + 3] + s.vbe1[c + 3]);
            *reinterpret_cast<__half2*>(&s.Xh[e * 264 + c]) =
                __halves2half2(__float2half_rn(o0), __float2half_rn(o1));
            *reinterpret_cast<__half2*>(&s.Xh[e * 264 + c + 2]) =
                __halves2half2(__float2half_rn(o2), __float2half_rn(o3));
        }
    }
    __syncthreads();

    // ---- warp tiling: 4 M-groups (16 edges) x 4 N-quarters (64 cols) ----
    const int mwid = wid & 3, nh = wid >> 2;
    const int aRow = (lane & 7) + (lane & 8);
    const int aK8 = (lane & 16) ? 8 : 0;
    const int bRow = (lane & 7) + ((lane & 16) ? 8 : 0);
    const int bK8 = (lane & 8) ? 8 : 0;
    const u32 xh_b = smem_u32(s.Xh);
    const u32 aoff = ((u32)(mwid * 16 + aRow) * 264 + aK8) * 2;
    const u32 bOff = ((u32)(nh * 64 + bRow) * 24 + bK8) * 2;
    const u32 bh_b0 = smem_u32(s.BH[0]) + bOff, bh_b1 = smem_u32(s.BH[1]) + bOff;
    const int sn = tid >> 1, sh = tid & 1;
    const int rr1 = mwid * 16 + g, rr2 = rr1 + 8;

    float d[8][4];

    // =========================== GEMM2 (We2, 1-term) ===========================
    {
#pragma unroll
        for (int i = 0; i < 8; i++)
#pragma unroll
            for (int j = 0; j < 4; j++) d[i][j] = 0.0f;

        uint4 pb;
        auto loadB = [&](int kc) {
            pb = *(const uint4*)(g_W2h + (size_t)sn * 256 + kc * 16 + sh * 8);
        };
        auto storeB = [&](int b) {
            *(uint4*)&s.BH[b][sn * 24 + sh * 8] = pb;
        };
        loadB(0); storeB(0);
        __syncthreads();

        for (int kc = 0; kc < 16; kc++) {
            if (kc < 15) loadB(kc + 1);
            const u32 bb = (kc & 1) ? bh_b1 : bh_b0;
            u32 a[4];
            ldsm4(a, xh_b + aoff + kc * 32);
#pragma unroll
            for (int ng = 0; ng < 4; ng++) {
                u32 bh[4];
                ldsm4(bh, bb + ng * 768);
                mma16816(d[2 * ng], a, bh);
                mma16816(d[2 * ng + 1], a, bh + 2);
            }
            if (kc < 15) storeB((kc + 1) & 1);
            __syncthreads();
        }

        // epilogue 2: edge_feat = silu(D+be2); float2 atomics; rewrite Xh
        int ri1 = s.rowI[rr1], ri2 = s.rowI[rr2];
#pragma unroll
        for (int ng = 0; ng < 4; ng++) {
#pragma unroll
            for (int hf = 0; hf < 2; hf++) {
                int c = nh * 64 + ng * 16 + hf * 8 + tg * 2;
                float* dd = d[2 * ng + hf];
                float o0 = silu_fast(dd[0] + s.vbe2[c]);
                float o1 = silu_fast(dd[1] + s.vbe2[c + 1]);
                float o2 = silu_fast(dd[2] + s.vbe2[c]);
                float o3 = silu_fast(dd[3] + s.vbe2[c + 1]);
                atomicAdd((float2*)&g_aggH[(size_t)ri1 * 256 + c], make_float2(o0, o1));
                atomicAdd((float2*)&g_aggH[(size_t)ri2 * 256 + c], make_float2(o2, o3));
                *reinterpret_cast<__half2*>(&s.Xh[rr1 * 264 + c]) =
                    __halves2half2(__float2half_rn(o0), __float2half_rn(o1));
                *reinterpret_cast<__half2*>(&s.Xh[rr2 * 264 + c]) =
                    __halves2half2(__float2half_rn(o2), __float2half_rn(o3));
            }
        }
    }
    __syncthreads();

    // =========================== GEMM3 (Wc1, 1-term) ===========================
    {
#pragma unroll
        for (int i = 0; i < 8; i++)
#pragma unroll
            for (int j = 0; j < 4; j++) d[i][j] = 0.0f;

        uint4 pb;
        auto loadB = [&](int kc) {
            pb = *(const uint4*)(g_Wch + (size_t)sn * 256 + kc * 16 + sh * 8);
        };
        auto storeB = [&](int b) {
            *(uint4*)&s.BH[b][sn * 24 + sh * 8] = pb;
        };
        loadB(0); storeB(0);
        __syncthreads();

        for (int kc = 0; kc < 16; kc++) {
            if (kc < 15) loadB(kc + 1);
            const u32 bb = (kc & 1) ? bh_b1 : bh_b0;
            u32 a[4];
            ldsm4(a, xh_b + aoff + kc * 32);
#pragma unroll
            for (int ng = 0; ng < 4; ng++) {
                u32 bh[4];
                ldsm4(bh, bb + ng * 768);
                mma16816(d[2 * ng], a, bh);
                mma16816(d[2 * ng + 1], a, bh + 2);
            }
            if (kc < 15) storeB((kc + 1) & 1);
            __syncthreads();
        }

        // epilogue 3: partial dot(silu(D+bc1), wc2) over this warp's N-quarter
        float p1 = 0.0f, p2 = 0.0f;
#pragma unroll
        for (int ng = 0; ng < 4; ng++) {
#pragma unroll
            for (int hf = 0; hf < 2; hf++) {
                int c = nh * 64 + ng * 16 + hf * 8 + tg * 2;
                float* dd = d[2 * ng + hf];
                p1 = fmaf(silu_fast(dd[0] + s.vbc1[c]), s.vwc2[c], p1);
                p1 = fmaf(silu_fast(dd[1] + s.vbc1[c + 1]), s.vwc2[c + 1], p1);
                p2 = fmaf(silu_fast(dd[2] + s.vbc1[c]), s.vwc2[c], p2);
                p2 = fmaf(silu_fast(dd[3] + s.vbc1[c + 1]), s.vwc2[c + 1], p2);
            }
        }
        p1 += __shfl_xor_sync(0xFFFFFFFF, p1, 1);
        p1 += __shfl_xor_sync(0xFFFFFFFF, p1, 2);
        p2 += __shfl_xor_sync(0xFFFFFFFF, p2, 1);
        p2 += __shfl_xor_sync(0xFFFFFFFF, p2, 2);
        if (tg == 0) {
            s.P[rr1 * 4 + nh] = p1;
            s.P[rr2 * 4 + nh] = p2;
        }
    }
    __syncthreads();

    // coord atomics
    if (tid < 64) {
        float scal = s.P[tid * 4 + 0] + s.P[tid * 4 + 1] + s.P[tid * 4 + 2] +
                     s.P[tid * 4 + 3] + __ldg(bc2);
        int ri = s.rowI[tid];
        atomicAdd(&g_aggC[ri * 3 + 0], s.cd[tid * 3 + 0] * scal);
        atomicAdd(&g_aggC[ri * 3 + 1], s.cd[tid * 3 + 1] * scal);
        atomicAdd(&g_aggC[ri * 3 + 2], s.cd[tid * 3 + 2] * scal);
        atomicAdd(&g_cnt[ri], 1.0f);
    }
}

// ---------------- node kernel ----------------
struct __align__(16) NSm { float X[64 * 260]; float B[32 * 256]; float A[64 * 33]; };

__global__ __launch_bounds__(256, 2) void node_kernel(
    const float* __restrict__ h, const float* __restrict__ coord,
    const float* __restrict__ Wn1, const float* __restrict__ bn1,
    const float* __restrict__ Wn2, const float* __restrict__ bn2,
    float* __restrict__ out) {
    extern __shared__ char smem_raw[];
    NSm& s = *reinterpret_cast<NSm*>(smem_raw);
    const int tid = threadIdx.x, tx = tid & 15, ty = tid >> 4, r0 = ty * 4;
    const int nb = blockIdx.x * 64;
    ull acc[4][8];
#pragma unroll
    for (int r = 0; r < 4; r++)
#pragma unroll
        for (int j = 0; j < 8; j++) acc[r][j] = 0ULL;
    const int rr = tid >> 2, kk = (tid & 3) * 8;
    const int nrow = nb + rr;
    const bool vA = nrow < Nn;

    for (int kc = 0; kc < 16; kc++) {
        const int kb = kc * 32;
        float4 v0 = make_float4(0.f, 0.f, 0.f, 0.f), v1 = v0;
        if (vA) {
            const float* src = (kc < 8) ? h + (size_t)nrow * 256 + kb + kk
                                        : g_aggH + (size_t)nrow * 256 + (kb - 256) + kk;
            v0 = *reinterpret_cast<const float4*>(src);
            v1 = *reinterpret_cast<const float4*>(src + 4);
        }
        float* da = &s.A[rr * 33 + kk];
        da[0] = v0.x; da[1] = v0.y; da[2] = v0.z; da[3] = v0.w;
        da[4] = v1.x; da[5] = v1.y; da[6] = v1.z; da[7] = v1.w;
        const float4* wsrc = reinterpret_cast<const float4*>(Wn1 + (size_t)kb * 256);
        float4* wdst = reinterpret_cast<float4*>(s.B);
#pragma unroll
        for (int i = 0; i < 8; i++) wdst[tid + 256 * i] = wsrc[tid + 256 * i];
        __syncthreads();
        mma_chunk<33>(&s.A[0], s.B, acc, tx, r0);
        __syncthreads();
    }
#pragma unroll
    for (int r = 0; r < 4; r++)
#pragma unroll
        for (int jj = 0; jj < 4; jj++) {
            int c0 = 4 * tx + 64 * jj;
            float2 p0 = unpack2(acc[r][2 * jj]), p1 = unpack2(acc[r][2 * jj + 1]);
            float4 o;
            o.x = silu_fast(p0.x + __ldg(&bn1[c0 + 0]));
            o.y = silu_fast(p0.y + __ldg(&bn1[c0 + 1]));
            o.z = silu_fast(p1.x + __ldg(&bn1[c0 + 2]));
            o.w = silu_fast(p1.y + __ldg(&bn1[c0 + 3]));
            *reinterpret_cast<float4*>(&s.X[(r0 + r) * 260 + c0]) = o;
            acc[r][2 * jj] = 0ULL; acc[r][2 * jj + 1] = 0ULL;
        }
    __syncthreads();
    for (int kc = 0; kc < 8; kc++) {
        const int kb = kc * 32;
        const float4* wsrc = reinterpret_cast<const float4*>(Wn2 + (size_t)kb * 256);
        float4* wdst = reinterpret_cast<float4*>(s.B);
#pragma unroll
        for (int i = 0; i < 8; i++) wdst[tid + 256 * i] = wsrc[tid + 256 * i];
        __syncthreads();
        mma_chunk<260>(&s.X[kb], s.B, acc, tx, r0);
        __syncthreads();
    }
#pragma unroll
    for (int r = 0; r < 4; r++) {
        int n = nb + r0 + r;
        if (n < Nn) {
#pragma unroll
            for (int jj = 0; jj < 4; jj++) {
                int c0 = 4 * tx + 64 * jj;
                float2 p0 = unpack2(acc[r][2 * jj]), p1 = unpack2(acc[r][2 * jj + 1]);
                float4 o;
                o.x = p0.x + __ldg(&bn2[c0 + 0]); o.y = p0.y + __ldg(&bn2[c0 + 1]);
                o.z = p1.x + __ldg(&bn2[c0 + 2]); o.w = p1.y + __ldg(&bn2[c0 + 3]);
                *reinterpret_cast<float4*>(&out[(size_t)n * 256 + c0]) = o;
            }
        }
    }
    if (tid < 64) {
        int n = nb + tid;
        if (n < Nn) {
            float inv = 1.0f / fmaxf(g_cnt[n], 1.0f);
#pragma unroll
            for (int dd = 0; dd < 3; dd++)
                out[(size_t)Nn * 256 + n * 3 + dd] = coord[n * 3 + dd] + g_aggC[n * 3 + dd] * inv;
        }
    }
}

// ---------------------------------------------------------------------------
extern "C" void kernel_launch(void* const* d_in, const int* in_sizes, int n_in,
                              void* d_out, int out_size) {
    const float* h     = (const float*)d_in[0];
    const float* coord = (const float*)d_in[1];
    const int*   ei    = (const int*)d_in[2];
    const float* We1   = (const float*)d_in[3];
    const float* be1   = (const float*)d_in[4];
    const float* We2   = (const float*)d_in[5];
    const float* be2   = (const float*)d_in[6];
    const float* Wn1   = (const float*)d_in[7];
    const float* bn1   = (const float*)d_in[8];
    const float* Wn2   = (const float*)d_in[9];
    const float* bn2   = (const float*)d_in[10];
    const float* Wc1   = (const float*)d_in[11];
    const float* bc1   = (const float*)d_in[12];
    const float* Wc2   = (const float*)d_in[13];
    const float* bc2   = (const float*)d_in[14];
    float* out = (float*)d_out;

    cudaFuncSetAttribute(edge_kernel, cudaFuncAttributeMaxDynamicSharedMemorySize, (int)sizeof(ESm));
    cudaFuncSetAttribute(node_kernel, cudaFuncAttributeMaxDynamicSharedMemorySize, (int)sizeof(NSm));
    cudaFuncSetAttribute(pcomp_kernel, cudaFuncAttributeMaxDynamicSharedMemorySize, (int)sizeof(PSm));

    zero_kernel<<<1280, 256>>>();
    prep_w<<<256, 256>>>(We2, 1);
    prep_w<<<256, 256>>>(Wc1, 2);
    pcomp_kernel<<<dim3((Nn + 63) / 64, 2), 256, sizeof(PSm)>>>(h, We1);
    edge_kernel<<<Ee / 64, 512, sizeof(ESm)>>>(coord, ei, We1, be1, be2, bc1, Wc2, bc2);
    node_kernel<<<(Nn + 63) / 64, 256, sizeof(NSm)>>>(h, coord, Wn1, bn1, Wn2, bn2, out);
}

// round 14
// speedup vs baseline: 1.7421x; 1.2454x over previous
#include <cuda_runtime.h>
#include <cuda_fp16.h>
#include <cstdint>

#define Nn 10000
#define Ee 320000

typedef unsigned long long ull;
typedef unsigned int u32;

// ---------------- device scratch ----------------
__device__ float g_aggH[Nn * 256];
__device__ float g_aggC[Nn * 3];
__device__ float g_cnt[Nn];
__device__ __align__(16) float g_P[(size_t)Nn * 512];
__device__ __align__(16) __half g_W2h[256 * 256];
__device__ __align__(16) __half g_Wch[256 * 256];

// ---------------- helpers ----------------
__device__ __forceinline__ u32 smem_u32(const void* p) {
    u32 a;
    asm("{ .reg .u64 t; cvta.to.shared.u64 t, %1; cvt.u32.u64 %0, t; }" : "=r"(a) : "l"(p));
    return a;
}
__device__ __forceinline__ void ldsm4(u32* r, u32 addr) {
    asm volatile("ldmatrix.sync.aligned.m8n8.x4.shared.b16 {%0,%1,%2,%3},[%4];"
                 : "=r"(r[0]), "=r"(r[1]), "=r"(r[2]), "=r"(r[3]) : "r"(addr));
}
__device__ __forceinline__ void mma16816(float* d, const u32* a, const u32* b) {
    asm volatile(
        "mma.sync.aligned.m16n8k16.row.col.f32.f16.f16.f32 "
        "{%0,%1,%2,%3},{%4,%5,%6,%7},{%8,%9},{%0,%1,%2,%3};"
        : "+f"(d[0]), "+f"(d[1]), "+f"(d[2]), "+f"(d[3])
        : "r"(a[0]), "r"(a[1]), "r"(a[2]), "r"(a[3]), "r"(b[0]), "r"(b[1]));
}

// MUFU-free silu
__device__ __forceinline__ float silu_fast(float x) {
    float v = fmaxf(-fabsf(x) * 1.4426950408889634f, -30.0f);
    float r = v + 12582912.0f;
    int ni = __float_as_int(r) - 0x4B400000;
    float f = v - (r - 12582912.0f);
    float p = 1.3333558146e-3f;
    p = fmaf(p, f, 9.6181291076e-3f);
    p = fmaf(p, f, 5.5504108664e-2f);
    p = fmaf(p, f, 2.4015967802e-1f);
    p = fmaf(p, f, 6.9314718056e-1f);
    p = fmaf(p, f, 1.0f);
    float z = __int_as_float(__float_as_int(p) + (ni << 23));
    float d = 1.0f + z;
    float y = __int_as_float(0x7EF311C3 - __float_as_int(d));
    y = y * fmaf(-d, y, 2.0f);
    y = y * fmaf(-d, y, 2.0f);
    y = y * fmaf(-d, y, 2.0f);
    float sig = (x >= 0.0f) ? y : (1.0f - y);
    return x * sig;
}

// ---------------- fp32 FFMA2 GEMM pieces ----------------
__device__ __forceinline__ ull pack_dup(float a) { ull r; asm("mov.b64 %0,{%1,%1};" : "=l"(r) : "f"(a)); return r; }
__device__ __forceinline__ float2 unpack2(ull v) { float2 r; asm("mov.b64 {%0,%1},%2;" : "=f"(r.x), "=f"(r.y) : "l"(v)); return r; }
__device__ __forceinline__ void fma2(ull& d, ull a, ull b) { asm("fma.rn.f32x2 %0,%1,%2,%0;" : "+l"(d) : "l"(a), "l"(b)); }

template <int AS>
__device__ __forceinline__ void mma_chunk(const float* __restrict__ A, const float* __restrict__ B,
                                          ull acc[4][8], int tx, int r0) {
#pragma unroll 8
    for (int k = 0; k < 32; k++) {
        ull ap[4];
#pragma unroll
        for (int r = 0; r < 4; r++) ap[r] = pack_dup(A[(r0 + r) * AS + k]);
        const float* brow = B + k * 256 + 4 * tx;
#pragma unroll
        for (int jj = 0; jj < 4; jj++) {
            ulonglong2 bv = *reinterpret_cast<const ulonglong2*>(brow + 64 * jj);
#pragma unroll
            for (int r = 0; r < 4; r++) { fma2(acc[r][2 * jj], ap[r], bv.x); fma2(acc[r][2 * jj + 1], ap[r], bv.y); }
        }
    }
}

// ---------------- prep kernels ----------------
__global__ void zero_kernel() {
    int idx = blockIdx.x * 256 + threadIdx.x, stride = gridDim.x * 256;
    for (int i = idx; i < Nn * 256; i += stride) g_aggH[i] = 0.0f;
    for (int i = idx; i < Nn * 3; i += stride) g_aggC[i] = 0.0f;
    for (int i = idx; i < Nn; i += stride) g_cnt[i] = 0.0f;
}
__global__ void prep_w(const float* __restrict__ W, int which) {
    int i = blockIdx.x * 256 + threadIdx.x;
    if (i >= 256 * 256) return;
    int k = i >> 8, n = i & 255;
    __half hb = __float2half_rn(W[i]);
    if (which == 1) g_W2h[(size_t)n * 256 + k] = hb;
    else            g_Wch[(size_t)n * 256 + k] = hb;
}

// ---------------- P = h @ [We1_top | We1_bot]  (fp32 exact) ----------------
struct __align__(16) PSm { float B[32 * 256]; float A[64 * 33]; };
__global__ __launch_bounds__(256, 2) void pcomp_kernel(const float* __restrict__ h,
                                                       const float* __restrict__ We1) {
    extern __shared__ char smr[];
    PSm& s = *reinterpret_cast<PSm*>(smr);
    const int tid = threadIdx.x, tx = tid & 15, ty = tid >> 4, r0 = ty * 4;
    const int nb = blockIdx.x * 64, hy = blockIdx.y;
    ull acc[4][8];
#pragma unroll
    for (int r = 0; r < 4; r++)
#pragma unroll
        for (int j = 0; j < 8; j++) acc[r][j] = 0ULL;
    const int rr = tid >> 2, kk = (tid & 3) * 8;
    const int nrow = nb + rr;
    const bool vA = nrow < Nn;

    for (int kc = 0; kc < 8; kc++) {
        const int kb = kc * 32;
        float4 v0 = make_float4(0.f, 0.f, 0.f, 0.f), v1 = v0;
        if (vA) {
            const float* src = h + (size_t)nrow * 256 + kb + kk;
            v0 = *reinterpret_cast<const float4*>(src);
            v1 = *reinterpret_cast<const float4*>(src + 4);
        }
        float* da = &s.A[rr * 33 + kk];
        da[0] = v0.x; da[1] = v0.y; da[2] = v0.z; da[3] = v0.w;
        da[4] = v1.x; da[5] = v1.y; da[6] = v1.z; da[7] = v1.w;
        const float4* wsrc = reinterpret_cast<const float4*>(We1 + (size_t)(hy * 256 + kb) * 256);
        float4* wdst = reinterpret_cast<float4*>(s.B);
#pragma unroll
        for (int i = 0; i < 8; i++) wdst[tid + 256 * i] = wsrc[tid + 256 * i];
        __syncthreads();
        mma_chunk<33>(&s.A[0], s.B, acc, tx, r0);
        __syncthreads();
    }
#pragma unroll
    for (int r = 0; r < 4; r++) {
        int n = nb + r0 + r;
        if (n < Nn) {
#pragma unroll
            for (int jj = 0; jj < 4; jj++) {
                int c0 = 4 * tx + 64 * jj;
                float2 p0 = unpack2(acc[r][2 * jj]), p1 = unpack2(acc[r][2 * jj + 1]);
                *reinterpret_cast<float4*>(&g_P[(size_t)n * 512 + hy * 256 + c0]) =
                    make_float4(p0.x, p0.y, p1.x, p1.y);
            }
        }
    }
}

// ---------------- fused edge kernel: 64 edges, 512 threads, occupancy 2 ----------------
struct __align__(128) ESm {
    __half Xh[64 * 264];        // 33792 B
    __half BH[2][256 * 40];     // 40960 B, double-buffered 32-wide K chunks
    float w512[256], vbe1[256], vbe2[256], vbc1[256], vwc2[256];
    float rad[64], cd[192], P[256];
    int rowI[64], colI[64];
};

__global__ __launch_bounds__(512, 2) void edge_kernel(
    const float* __restrict__ coord, const int* __restrict__ ei,
    const float* __restrict__ We1, const float* __restrict__ be1,
    const float* __restrict__ be2, const float* __restrict__ bc1,
    const float* __restrict__ Wc2, const float* __restrict__ bc2) {
    extern __shared__ char smr[];
    ESm& s = *reinterpret_cast<ESm*>(smr);
    const int tid = threadIdx.x, wid = tid >> 5, lane = tid & 31;
    const int g = lane >> 2, tg = lane & 3;
    const int eb = blockIdx.x * 64;

    if (tid < 64) {
        int e = eb + tid;
        int ri = ei[e], ci = ei[Ee + e];
        s.rowI[tid] = ri; s.colI[tid] = ci;
        float dx = coord[ri * 3 + 0] - coord[ci * 3 + 0];
        float dy = coord[ri * 3 + 1] - coord[ci * 3 + 1];
        float dz = coord[ri * 3 + 2] - coord[ci * 3 + 2];
        s.cd[tid * 3 + 0] = dx; s.cd[tid * 3 + 1] = dy; s.cd[tid * 3 + 2] = dz;
        s.rad[tid] = dx * dx + dy * dy + dz * dz;
    }
    if (tid < 256) {
        s.w512[tid] = We1[512 * 256 + tid];
        s.vbe1[tid] = be1[tid];
        s.vbe2[tid] = be2[tid];
        s.vbc1[tid] = bc1[tid];
        s.vwc2[tid] = Wc2[tid];
    }
    __syncthreads();

    // ---- phase 1 (COALESCED): X = silu(P[row]+P[col|256]+rad*w512+be1) ----
    {
        int e = tid >> 3, w8 = tid & 7;
        const float4* pr = (const float4*)(g_P + (size_t)s.rowI[e] * 512) + w8;
        const float4* pc = (const float4*)(g_P + (size_t)s.colI[e] * 512 + 256) + w8;
        float radr = s.rad[e];
#pragma unroll
        for (int jj = 0; jj < 8; jj++) {
            float4 a = pr[jj * 8], b = pc[jj * 8];
            int c = w8 * 4 + jj * 32;
            float o0 = silu_fast(a.x + b.x + radr * s.w512[c + 0] + s.vbe1[c + 0]);
            float o1 = silu_fast(a.y + b.y + radr * s.w512[c + 1] + s.vbe1[c + 1]);
            float o2 = silu_fast(a.z + b.z + radr * s.w512[c + 2] + s.vbe1[c + 2]);
            float o3 = silu_fast(a.w + b.w + radr * s.w512[c + 3] + s.vbe1[c + 3]);
            *reinterpret_cast<__half2*>(&s.Xh[e * 264 + c]) =
                __halves2half2(__float2half_rn(o0), __float2half_rn(o1));
            *reinterpret_cast<__half2*>(&s.Xh[e * 264 + c + 2]) =
                __halves2half2(__float2half_rn(o2), __float2half_rn(o3));
        }
    }
    __syncthreads();

    // ---- warp tiling: 4 M-groups (16 edges) x 4 N-quarters (64 cols) ----
    const int mwid = wid & 3, nh = wid >> 2;
    const int aRow = (lane & 7) + (lane & 8);
    const int aK8 = (lane & 16) ? 8 : 0;
    const int bRow = (lane & 7) + ((lane & 16) ? 8 : 0);
    const int bK8 = (lane & 8) ? 8 : 0;
    const u32 xh_b = smem_u32(s.Xh);
    const u32 aoff = ((u32)(mwid * 16 + aRow) * 264 + aK8) * 2;
    const u32 bOff = ((u32)(nh * 64 + bRow) * 40 + bK8) * 2;
    const u32 bh_b0 = smem_u32(s.BH[0]) + bOff, bh_b1 = smem_u32(s.BH[1]) + bOff;
    const int sn = tid >> 1, sh = tid & 1;
    const int rr1 = mwid * 16 + g, rr2 = rr1 + 8;

    float d[8][4];

    // =========================== GEMM2 (We2, 1-term) ===========================
    {
#pragma unroll
        for (int i = 0; i < 8; i++)
#pragma unroll
            for (int j = 0; j < 4; j++) d[i][j] = 0.0f;

        uint4 pb0, pb1;
        auto loadB = [&](int kc) {
            const uint4* b4 = (const uint4*)(g_W2h + (size_t)sn * 256 + kc * 32 + sh * 16);
            pb0 = b4[0]; pb1 = b4[1];
        };
        auto storeB = [&](int b) {
            *(uint4*)&s.BH[b][sn * 40 + sh * 16] = pb0;
            *(uint4*)&s.BH[b][sn * 40 + sh * 16 + 8] = pb1;
        };
        loadB(0); storeB(0);
        __syncthreads();

        for (int kc = 0; kc < 8; kc++) {
            if (kc < 7) loadB(kc + 1);
            const u32 bb = (kc & 1) ? bh_b1 : bh_b0;
#pragma unroll
            for (int ks = 0; ks < 2; ks++) {
                u32 a[4];
                ldsm4(a, xh_b + aoff + (kc * 32 + ks * 16) * 2);
#pragma unroll
                for (int ng = 0; ng < 4; ng++) {
                    u32 bh[4];
                    ldsm4(bh, bb + ng * 1280 + ks * 32);
                    mma16816(d[2 * ng], a, bh);
                    mma16816(d[2 * ng + 1], a, bh + 2);
                }
            }
            if (kc < 7) storeB((kc + 1) & 1);
            __syncthreads();
        }

        // epilogue 2: edge_feat = silu(D+be2); float2 atomics; rewrite Xh
        int ri1 = s.rowI[rr1], ri2 = s.rowI[rr2];
#pragma unroll
        for (int ng = 0; ng < 4; ng++) {
#pragma unroll
            for (int hf = 0; hf < 2; hf++) {
                int c = nh * 64 + ng * 16 + hf * 8 + tg * 2;
                float* dd = d[2 * ng + hf];
                float o0 = silu_fast(dd[0] + s.vbe2[c]);
                float o1 = silu_fast(dd[1] + s.vbe2[c + 1]);
                float o2 = silu_fast(dd[2] + s.vbe2[c]);
                float o3 = silu_fast(dd[3] + s.vbe2[c + 1]);
                atomicAdd((float2*)&g_aggH[(size_t)ri1 * 256 + c], make_float2(o0, o1));
                atomicAdd((float2*)&g_aggH[(size_t)ri2 * 256 + c], make_float2(o2, o3));
                *reinterpret_cast<__half2*>(&s.Xh[rr1 * 264 + c]) =
                    __halves2half2(__float2half_rn(o0), __float2half_rn(o1));
                *reinterpret_cast<__half2*>(&s.Xh[rr2 * 264 + c]) =
                    __halves2half2(__float2half_rn(o2), __float2half_rn(o3));
            }
        }
    }
    __syncthreads();

    // =========================== GEMM3 (Wc1, 1-term) ===========================
    {
#pragma unroll
        for (int i = 0; i < 8; i++)
#pragma unroll
            for (int j = 0; j < 4; j++) d[i][j] = 0.0f;

        uint4 pb0, pb1;
        auto loadB = [&](int kc) {
            const uint4* b4 = (const uint4*)(g_Wch + (size_t)sn * 256 + kc * 32 + sh * 16);
            pb0 = b4[0]; pb1 = b4[1];
        };
        auto storeB = [&](int b) {
            *(uint4*)&s.BH[b][sn * 40 + sh * 16] = pb0;
            *(uint4*)&s.BH[b][sn * 40 + sh * 16 + 8] = pb1;
        };
        loadB(0); storeB(0);
        __syncthreads();

        for (int kc = 0; kc < 8; kc++) {
            if (kc < 7) loadB(kc + 1);
            const u32 bb = (kc & 1) ? bh_b1 : bh_b0;
#pragma unroll
            for (int ks = 0; ks < 2; ks++) {
                u32 a[4];
                ldsm4(a, xh_b + aoff + (kc * 32 + ks * 16) * 2);
#pragma unroll
                for (int ng = 0; ng < 4; ng++) {
                    u32 bh[4];
                    ldsm4(bh, bb + ng * 1280 + ks * 32);
                    mma16816(d[2 * ng], a, bh);
                    mma16816(d[2 * ng + 1], a, bh + 2);
                }
            }
            if (kc < 7) storeB((kc + 1) & 1);
            __syncthreads();
        }

        // epilogue 3: partial dot(silu(D+bc1), wc2) over this warp's N-quarter
        float p1 = 0.0f, p2 = 0.0f;
#pragma unroll
        for (int ng = 0; ng < 4; ng++) {
#pragma unroll
            for (int hf = 0; hf < 2; hf++) {
                int c = nh * 64 + ng * 16 + hf * 8 + tg * 2;
                float* dd = d[2 * ng + hf];
                p1 = fmaf(silu_fast(dd[0] + s.vbc1[c]), s.vwc2[c], p1);
                p1 = fmaf(silu_fast(dd[1] + s.vbc1[c + 1]), s.vwc2[c + 1], p1);
                p2 = fmaf(silu_fast(dd[2] + s.vbc1[c]), s.vwc2[c], p2);
                p2 = fmaf(silu_fast(dd[3] + s.vbc1[c + 1]), s.vwc2[c + 1], p2);
            }
        }
        p1 += __shfl_xor_sync(0xFFFFFFFF, p1, 1);
        p1 += __shfl_xor_sync(0xFFFFFFFF, p1, 2);
        p2 += __shfl_xor_sync(0xFFFFFFFF, p2, 1);
        p2 += __shfl_xor_sync(0xFFFFFFFF, p2, 2);
        if (tg == 0) {
            s.P[rr1 * 4 + nh] = p1;
            s.P[rr2 * 4 + nh] = p2;
        }
    }
    __syncthreads();

    // coord atomics
    if (tid < 64) {
        float scal = s.P[tid * 4 + 0] + s.P[tid * 4 + 1] + s.P[tid * 4 + 2] +
                     s.P[tid * 4 + 3] + __ldg(bc2);
        int ri = s.rowI[tid];
        atomicAdd(&g_aggC[ri * 3 + 0], s.cd[tid * 3 + 0] * scal);
        atomicAdd(&g_aggC[ri * 3 + 1], s.cd[tid * 3 + 1] * scal);
        atomicAdd(&g_aggC[ri * 3 + 2], s.cd[tid * 3 + 2] * scal);
        atomicAdd(&g_cnt[ri], 1.0f);
    }
}

// ---------------- node kernel ----------------
struct __align__(16) NSm { float X[64 * 260]; float B[32 * 256]; float A[64 * 33]; };

__global__ __launch_bounds__(256, 2) void node_kernel(
    const float* __restrict__ h, const float* __restrict__ coord,
    const float* __restrict__ Wn1, const float* __restrict__ bn1,
    const float* __restrict__ Wn2, const float* __restrict__ bn2,
    float* __restrict__ out) {
    extern __shared__ char smem_raw[];
    NSm& s = *reinterpret_cast<NSm*>(smem_raw);
    const int tid = threadIdx.x, tx = tid & 15, ty = tid >> 4, r0 = ty * 4;
    const int nb = blockIdx.x * 64;
    ull acc[4][8];
#pragma unroll
    for (int r = 0; r < 4; r++)
#pragma unroll
        for (int j = 0; j < 8; j++) acc[r][j] = 0ULL;
    const int rr = tid >> 2, kk = (tid & 3) * 8;
    const int nrow = nb + rr;
    const bool vA = nrow < Nn;

    for (int kc = 0; kc < 16; kc++) {
        const int kb = kc * 32;
        float4 v0 = make_float4(0.f, 0.f, 0.f, 0.f), v1 = v0;
        if (vA) {
            const float* src = (kc < 8) ? h + (size_t)nrow * 256 + kb + kk
                                        : g_aggH + (size_t)nrow * 256 + (kb - 256) + kk;
            v0 = *reinterpret_cast<const float4*>(src);
            v1 = *reinterpret_cast<const float4*>(src + 4);
        }
        float* da = &s.A[rr * 33 + kk];
        da[0] = v0.x; da[1] = v0.y; da[2] = v0.z; da[3] = v0.w;
        da[4] = v1.x; da[5] = v1.y; da[6] = v1.z; da[7] = v1.w;
        const float4* wsrc = reinterpret_cast<const float4*>(Wn1 + (size_t)kb * 256);
        float4* wdst = reinterpret_cast<float4*>(s.B);
#pragma unroll
        for (int i = 0; i < 8; i++) wdst[tid + 256 * i] = wsrc[tid + 256 * i];
        __syncthreads();
        mma_chunk<33>(&s.A[0], s.B, acc, tx, r0);
        __syncthreads();
    }
#pragma unroll
    for (int r = 0; r < 4; r++)
#pragma unroll
        for (int jj = 0; jj < 4; jj++) {
            int c0 = 4 * tx + 64 * jj;
            float2 p0 = unpack2(acc[r][2 * jj]), p1 = unpack2(acc[r][2 * jj + 1]);
            float4 o;
            o.x = silu_fast(p0.x + __ldg(&bn1[c0 + 0]));
            o.y = silu_fast(p0.y + __ldg(&bn1[c0 + 1]));
            o.z = silu_fast(p1.x + __ldg(&bn1[c0 + 2]));
            o.w = silu_fast(p1.y + __ldg(&bn1[c0 + 3]));
            *reinterpret_cast<float4*>(&s.X[(r0 + r) * 260 + c0]) = o;
            acc[r][2 * jj] = 0ULL; acc[r][2 * jj + 1] = 0ULL;
        }
    __syncthreads();
    for (int kc = 0; kc < 8; kc++) {
        const int kb = kc * 32;
        const float4* wsrc = reinterpret_cast<const float4*>(Wn2 + (size_t)kb * 256);
        float4* wdst = reinterpret_cast<float4*>(s.B);
#pragma unroll
        for (int i = 0; i < 8; i++) wdst[tid + 256 * i] = wsrc[tid + 256 * i];
        __syncthreads();
        mma_chunk<260>(&s.X[kb], s.B, acc, tx, r0);
        __syncthreads();
    }
#pragma unroll
    for (int r = 0; r < 4; r++) {
        int n = nb + r0 + r;
        if (n < Nn) {
#pragma unroll
            for (int jj = 0; jj < 4; jj++) {
                int c0 = 4 * tx + 64 * jj;
                float2 p0 = unpack2(acc[r][2 * jj]), p1 = unpack2(acc[r][2 * jj + 1]);
                float4 o;
                o.x = p0.x + __ldg(&bn2[c0 + 0]); o.y = p0.y + __ldg(&bn2[c0 + 1]);
                o.z = p1.x + __ldg(&bn2[c0 + 2]); o.w = p1.y + __ldg(&bn2[c0 + 3]);
                *reinterpret_cast<float4*>(&out[(size_t)n * 256 + c0]) = o;
            }
        }
    }
    if (tid < 64) {
        int n = nb + tid;
        if (n < Nn) {
            float inv = 1.0f / fmaxf(g_cnt[n], 1.0f);
#pragma unroll
            for (int dd = 0; dd < 3; dd++)
                out[(size_t)Nn * 256 + n * 3 + dd] = coord[n * 3 + dd] + g_aggC[n * 3 + dd] * inv;
        }
    }
}

// ---------------------------------------------------------------------------
extern "C" void kernel_launch(void* const* d_in, const int* in_sizes, int n_in,
                              void* d_out, int out_size) {
    const float* h     = (const float*)d_in[0];
    const float* coord = (const float*)d_in[1];
    const int*   ei    = (const int*)d_in[2];
    const float* We1   = (const float*)d_in[3];
    const float* be1   = (const float*)d_in[4];
    const float* We2   = (const float*)d_in[5];
    const float* be2   = (const float*)d_in[6];
    const float* Wn1   = (const float*)d_in[7];
    const float* bn1   = (const float*)d_in[8];
    const float* Wn2   = (const float*)d_in[9];
    const float* bn2   = (const float*)d_in[10];
    const float* Wc1   = (const float*)d_in[11];
    const float* bc1   = (const float*)d_in[12];
    const float* Wc2   = (const float*)d_in[13];
    const float* bc2   = (const float*)d_in[14];
    float* out = (float*)d_out;

    cudaFuncSetAttribute(edge_kernel, cudaFuncAttributeMaxDynamicSharedMemorySize, (int)sizeof(ESm));
    cudaFuncSetAttribute(node_kernel, cudaFuncAttributeMaxDynamicSharedMemorySize, (int)sizeof(NSm));
    cudaFuncSetAttribute(pcomp_kernel, cudaFuncAttributeMaxDynamicSharedMemorySize, (int)sizeof(PSm));

    zero_kernel<<<1280, 256>>>();
    prep_w<<<256, 256>>>(We2, 1);
    prep_w<<<256, 256>>>(Wc1, 2);
    pcomp_kernel<<<dim3((Nn + 63) / 64, 2), 256, sizeof(PSm)>>>(h, We1);
    edge_kernel<<<Ee / 64, 512, sizeof(ESm)>>>(coord, ei, We1, be1, be2, bc1, Wc2, bc2);
    node_kernel<<<(Nn + 63) / 64, 256, sizeof(NSm)>>>(h, coord, Wn1, bn1, Wn2, bn2, out);
}

// round 15
// speedup vs baseline: 1.8404x; 1.0564x over previous
#include <cuda_runtime.h>
#include <cuda_fp16.h>
#include <cstdint>

#define Nn 10000
#define Ee 320000

typedef unsigned long long ull;
typedef unsigned int u32;

// ---------------- device scratch ----------------
__device__ float g_aggH[Nn * 256];
__device__ float g_aggC[Nn * 3];
__device__ float g_cnt[Nn];
__device__ __align__(16) float g_P[(size_t)Nn * 512];
__device__ __align__(16) __half g_W2h[256 * 256];
__device__ __align__(16) __half g_Wch[256 * 256];

// ---------------- helpers ----------------
__device__ __forceinline__ u32 smem_u32(const void* p) {
    u32 a;
    asm("{ .reg .u64 t; cvta.to.shared.u64 t, %1; cvt.u32.u64 %0, t; }" : "=r"(a) : "l"(p));
    return a;
}
__device__ __forceinline__ void ldsm4(u32* r, u32 addr) {
    asm volatile("ldmatrix.sync.aligned.m8n8.x4.shared.b16 {%0,%1,%2,%3},[%4];"
                 : "=r"(r[0]), "=r"(r[1]), "=r"(r[2]), "=r"(r[3]) : "r"(addr));
}
__device__ __forceinline__ void mma16816(float* d, const u32* a, const u32* b) {
    asm volatile(
        "mma.sync.aligned.m16n8k16.row.col.f32.f16.f16.f32 "
        "{%0,%1,%2,%3},{%4,%5,%6,%7},{%8,%9},{%0,%1,%2,%3};"
        : "+f"(d[0]), "+f"(d[1]), "+f"(d[2]), "+f"(d[3])
        : "r"(a[0]), "r"(a[1]), "r"(a[2]), "r"(a[3]), "r"(b[0]), "r"(b[1]));
}

// HW silu: 3 FMA-pipe ops + 2 MUFU (ex2.approx + rcp.approx), rel err ~2^-22
__device__ __forceinline__ float silu_fast(float x) {
    float e;
    asm("ex2.approx.f32 %0, %1;" : "=f"(e) : "f"(x * -1.4426950408889634f));
    float r;
    asm("rcp.approx.f32 %0, %1;" : "=f"(r) : "f"(1.0f + e));
    return x * r;
}

// ---------------- fp32 FFMA2 GEMM pieces ----------------
__device__ __forceinline__ ull pack_dup(float a) { ull r; asm("mov.b64 %0,{%1,%1};" : "=l"(r) : "f"(a)); return r; }
__device__ __forceinline__ float2 unpack2(ull v) { float2 r; asm("mov.b64 {%0,%1},%2;" : "=f"(r.x), "=f"(r.y) : "l"(v)); return r; }
__device__ __forceinline__ void fma2(ull& d, ull a, ull b) { asm("fma.rn.f32x2 %0,%1,%2,%0;" : "+l"(d) : "l"(a), "l"(b)); }

template <int AS>
__device__ __forceinline__ void mma_chunk(const float* __restrict__ A, const float* __restrict__ B,
                                          ull acc[4][8], int tx, int r0) {
#pragma unroll 8
    for (int k = 0; k < 32; k++) {
        ull ap[4];
#pragma unroll
        for (int r = 0; r < 4; r++) ap[r] = pack_dup(A[(r0 + r) * AS + k]);
        const float* brow = B + k * 256 + 4 * tx;
#pragma unroll
        for (int jj = 0; jj < 4; jj++) {
            ulonglong2 bv = *reinterpret_cast<const ulonglong2*>(brow + 64 * jj);
#pragma unroll
            for (int r = 0; r < 4; r++) { fma2(acc[r][2 * jj], ap[r], bv.x); fma2(acc[r][2 * jj + 1], ap[r], bv.y); }
        }
    }
}

// ---------------- prep kernels ----------------
__global__ void zero_kernel() {
    int idx = blockIdx.x * 256 + threadIdx.x, stride = gridDim.x * 256;
    for (int i = idx; i < Nn * 256; i += stride) g_aggH[i] = 0.0f;
    for (int i = idx; i < Nn * 3; i += stride) g_aggC[i] = 0.0f;
    for (int i = idx; i < Nn; i += stride) g_cnt[i] = 0.0f;
}
__global__ void prep_w(const float* __restrict__ W, int which) {
    int i = blockIdx.x * 256 + threadIdx.x;
    if (i >= 256 * 256) return;
    int k = i >> 8, n = i & 255;
    __half hb = __float2half_rn(W[i]);
    if (which == 1) g_W2h[(size_t)n * 256 + k] = hb;
    else            g_Wch[(size_t)n * 256 + k] = hb;
}

// ---------------- P = h @ [We1_top | We1_bot]  (fp32 exact) ----------------
struct __align__(16) PSm { float B[32 * 256]; float A[64 * 33]; };
__global__ __launch_bounds__(256, 2) void pcomp_kernel(const float* __restrict__ h,
                                                       const float* __restrict__ We1) {
    extern __shared__ char smr[];
    PSm& s = *reinterpret_cast<PSm*>(smr);
    const int tid = threadIdx.x, tx = tid & 15, ty = tid >> 4, r0 = ty * 4;
    const int nb = blockIdx.x * 64, hy = blockIdx.y;
    ull acc[4][8];
#pragma unroll
    for (int r = 0; r < 4; r++)
#pragma unroll
        for (int j = 0; j < 8; j++) acc[r][j] = 0ULL;
    const int rr = tid >> 2, kk = (tid & 3) * 8;
    const int nrow = nb + rr;
    const bool vA = nrow < Nn;

    for (int kc = 0; kc < 8; kc++) {
        const int kb = kc * 32;
        float4 v0 = make_float4(0.f, 0.f, 0.f, 0.f), v1 = v0;
        if (vA) {
            const float* src = h + (size_t)nrow * 256 + kb + kk;
            v0 = *reinterpret_cast<const float4*>(src);
            v1 = *reinterpret_cast<const float4*>(src + 4);
        }
        float* da = &s.A[rr * 33 + kk];
        da[0] = v0.x; da[1] = v0.y; da[2] = v0.z; da[3] = v0.w;
        da[4] = v1.x; da[5] = v1.y; da[6] = v1.z; da[7] = v1.w;
        const float4* wsrc = reinterpret_cast<const float4*>(We1 + (size_t)(hy * 256 + kb) * 256);
        float4* wdst = reinterpret_cast<float4*>(s.B);
#pragma unroll
        for (int i = 0; i < 8; i++) wdst[tid + 256 * i] = wsrc[tid + 256 * i];
        __syncthreads();
        mma_chunk<33>(&s.A[0], s.B, acc, tx, r0);
        __syncthreads();
    }
#pragma unroll
    for (int r = 0; r < 4; r++) {
        int n = nb + r0 + r;
        if (n < Nn) {
#pragma unroll
            for (int jj = 0; jj < 4; jj++) {
                int c0 = 4 * tx + 64 * jj;
                float2 p0 = unpack2(acc[r][2 * jj]), p1 = unpack2(acc[r][2 * jj + 1]);
                *reinterpret_cast<float4*>(&g_P[(size_t)n * 512 + hy * 256 + c0]) =
                    make_float4(p0.x, p0.y, p1.x, p1.y);
            }
        }
    }
}

// ---------------- fused edge kernel: 64 edges, 512 threads, occupancy 2 ----------------
struct __align__(128) ESm {
    __half Xh[64 * 264];        // 33792 B
    __half BH[2][256 * 40];     // 40960 B, double-buffered 32-wide K chunks
    float w512[256], vbe1[256], vbe2[256], vbc1[256], vwc2[256];
    float rad[64], cd[192], P[256];
    int rowI[64], colI[64];
};

__global__ __launch_bounds__(512, 2) void edge_kernel(
    const float* __restrict__ coord, const int* __restrict__ ei,
    const float* __restrict__ We1, const float* __restrict__ be1,
    const float* __restrict__ be2, const float* __restrict__ bc1,
    const float* __restrict__ Wc2, const float* __restrict__ bc2) {
    extern __shared__ char smr[];
    ESm& s = *reinterpret_cast<ESm*>(smr);
    const int tid = threadIdx.x, wid = tid >> 5, lane = tid & 31;
    const int g = lane >> 2, tg = lane & 3;
    const int eb = blockIdx.x * 64;

    if (tid < 64) {
        int e = eb + tid;
        int ri = ei[e], ci = ei[Ee + e];
        s.rowI[tid] = ri; s.colI[tid] = ci;
        float dx = coord[ri * 3 + 0] - coord[ci * 3 + 0];
        float dy = coord[ri * 3 + 1] - coord[ci * 3 + 1];
        float dz = coord[ri * 3 + 2] - coord[ci * 3 + 2];
        s.cd[tid * 3 + 0] = dx; s.cd[tid * 3 + 1] = dy; s.cd[tid * 3 + 2] = dz;
        s.rad[tid] = dx * dx + dy * dy + dz * dz;
    }
    if (tid < 256) {
        s.w512[tid] = We1[512 * 256 + tid];
        s.vbe1[tid] = be1[tid];
        s.vbe2[tid] = be2[tid];
        s.vbc1[tid] = bc1[tid];
        s.vwc2[tid] = Wc2[tid];
    }
    __syncthreads();

    // ---- phase 1 (coalesced): X = silu(P[row]+P[col|256]+rad*w512+be1) ----
    {
        int e = tid >> 3, w8 = tid & 7;
        const float4* pr = (const float4*)(g_P + (size_t)s.rowI[e] * 512) + w8;
        const float4* pc = (const float4*)(g_P + (size_t)s.colI[e] * 512 + 256) + w8;
        float radr = s.rad[e];
#pragma unroll
        for (int jj = 0; jj < 8; jj++) {
            float4 a = pr[jj * 8], b = pc[jj * 8];
            int c = w8 * 4 + jj * 32;
            float o0 = silu_fast(a.x + b.x + radr * s.w512[c + 0] + s.vbe1[c + 0]);
            float o1 = silu_fast(a.y + b.y + radr * s.w512[c + 1] + s.vbe1[c + 1]);
            float o2 = silu_fast(a.z + b.z + radr * s.w512[c + 2] + s.vbe1[c + 2]);
            float o3 = silu_fast(a.w + b.w + radr * s.w512[c + 3] + s.vbe1[c + 3]);
            *reinterpret_cast<__half2*>(&s.Xh[e * 264 + c]) =
                __halves2half2(__float2half_rn(o0), __float2half_rn(o1));
            *reinterpret_cast<__half2*>(&s.Xh[e * 264 + c + 2]) =
                __halves2half2(__float2half_rn(o2), __float2half_rn(o3));
        }
    }
    __syncthreads();

    // ---- warp tiling: 4 M-groups (16 edges) x 4 N-quarters (64 cols) ----
    const int mwid = wid & 3, nh = wid >> 2;
    const int aRow = (lane & 7) + (lane & 8);
    const int aK8 = (lane & 16) ? 8 : 0;
    const int bRow = (lane & 7) + ((lane & 16) ? 8 : 0);
    const int bK8 = (lane & 8) ? 8 : 0;
    const u32 xh_b = smem_u32(s.Xh);
    const u32 aoff = ((u32)(mwid * 16 + aRow) * 264 + aK8) * 2;
    const u32 bOff = ((u32)(nh * 64 + bRow) * 40 + bK8) * 2;
    const u32 bh_b0 = smem_u32(s.BH[0]) + bOff, bh_b1 = smem_u32(s.BH[1]) + bOff;
    const int sn = tid >> 1, sh = tid & 1;
    const int rr1 = mwid * 16 + g, rr2 = rr1 + 8;

    float d[8][4];

    // =========================== GEMM2 (We2, 1-term) ===========================
    {
#pragma unroll
        for (int i = 0; i < 8; i++)
#pragma unroll
            for (int j = 0; j < 4; j++) d[i][j] = 0.0f;

        uint4 pb0, pb1;
        auto loadB = [&](int kc) {
            const uint4* b4 = (const uint4*)(g_W2h + (size_t)sn * 256 + kc * 32 + sh * 16);
            pb0 = b4[0]; pb1 = b4[1];
        };
        auto storeB = [&](int b) {
            *(uint4*)&s.BH[b][sn * 40 + sh * 16] = pb0;
            *(uint4*)&s.BH[b][sn * 40 + sh * 16 + 8] = pb1;
        };
        loadB(0); storeB(0);
        __syncthreads();

        for (int kc = 0; kc < 8; kc++) {
            if (kc < 7) loadB(kc + 1);
            const u32 bb = (kc & 1) ? bh_b1 : bh_b0;
#pragma unroll
            for (int ks = 0; ks < 2; ks++) {
                u32 a[4];
                ldsm4(a, xh_b + aoff + (kc * 32 + ks * 16) * 2);
#pragma unroll
                for (int ng = 0; ng < 4; ng++) {
                    u32 bh[4];
                    ldsm4(bh, bb + ng * 1280 + ks * 32);
                    mma16816(d[2 * ng], a, bh);
                    mma16816(d[2 * ng + 1], a, bh + 2);
                }
            }
            if (kc < 7) storeB((kc + 1) & 1);
            __syncthreads();
        }

        // epilogue 2: edge_feat = silu(D+be2); float2 atomics; rewrite Xh
        int ri1 = s.rowI[rr1], ri2 = s.rowI[rr2];
#pragma unroll
        for (int ng = 0; ng < 4; ng++) {
#pragma unroll
            for (int hf = 0; hf < 2; hf++) {
                int c = nh * 64 + ng * 16 + hf * 8 + tg * 2;
                float* dd = d[2 * ng + hf];
                float o0 = silu_fast(dd[0] + s.vbe2[c]);
                float o1 = silu_fast(dd[1] + s.vbe2[c + 1]);
                float o2 = silu_fast(dd[2] + s.vbe2[c]);
                float o3 = silu_fast(dd[3] + s.vbe2[c + 1]);
                atomicAdd((float2*)&g_aggH[(size_t)ri1 * 256 + c], make_float2(o0, o1));
                atomicAdd((float2*)&g_aggH[(size_t)ri2 * 256 + c], make_float2(o2, o3));
                *reinterpret_cast<__half2*>(&s.Xh[rr1 * 264 + c]) =
                    __halves2half2(__float2half_rn(o0), __float2half_rn(o1));
                *reinterpret_cast<__half2*>(&s.Xh[rr2 * 264 + c]) =
                    __halves2half2(__float2half_rn(o2), __float2half_rn(o3));
            }
        }
    }
    __syncthreads();

    // =========================== GEMM3 (Wc1, 1-term) ===========================
    {
#pragma unroll
        for (int i = 0; i < 8; i++)
#pragma unroll
            for (int j = 0; j < 4; j++) d[i][j] = 0.0f;

        uint4 pb0, pb1;
        auto loadB = [&](int kc) {
            const uint4* b4 = (const uint4*)(g_Wch + (size_t)sn * 256 + kc * 32 + sh * 16);
            pb0 = b4[0]; pb1 = b4[1];
        };
        auto storeB = [&](int b) {
            *(uint4*)&s.BH[b][sn * 40 + sh * 16] = pb0;
            *(uint4*)&s.BH[b][sn * 40 + sh * 16 + 8] = pb1;
        };
        loadB(0); storeB(0);
        __syncthreads();

        for (int kc = 0; kc < 8; kc++) {
            if (kc < 7) loadB(kc + 1);
            const u32 bb = (kc & 1) ? bh_b1 : bh_b0;
#pragma unroll
            for (int ks = 0; ks < 2; ks++) {
                u32 a[4];
                ldsm4(a, xh_b + aoff + (kc * 32 + ks * 16) * 2);
#pragma unroll
                for (int ng = 0; ng < 4; ng++) {
                    u32 bh[4];
                    ldsm4(bh, bb + ng * 1280 + ks * 32);
                    mma16816(d[2 * ng], a, bh);
                    mma16816(d[2 * ng + 1], a, bh + 2);
                }
            }
            if (kc < 7) storeB((kc + 1) & 1);
            __syncthreads();
        }

        // epilogue 3: partial dot(silu(D+bc1), wc2) over this warp's N-quarter
        float p1 = 0.0f, p2 = 0.0f;
#pragma unroll
        for (int ng = 0; ng < 4; ng++) {
#pragma unroll
            for (int hf = 0; hf < 2; hf++) {
                int c = nh * 64 + ng * 16 + hf * 8 + tg * 2;
                float* dd = d[2 * ng + hf];
                p1 = fmaf(silu_fast(dd[0] + s.vbc1[c]), s.vwc2[c], p1);
                p1 = fmaf(silu_fast(dd[1] + s.vbc1[c + 1]), s.vwc2[c + 1], p1);
                p2 = fmaf(silu_fast(dd[2] + s.vbc1[c]), s.vwc2[c], p2);
                p2 = fmaf(silu_fast(dd[3] + s.vbc1[c + 1]), s.vwc2[c + 1], p2);
            }
        }
        p1 += __shfl_xor_sync(0xFFFFFFFF, p1, 1);
        p1 += __shfl_xor_sync(0xFFFFFFFF, p1, 2);
        p2 += __shfl_xor_sync(0xFFFFFFFF, p2, 1);
        p2 += __shfl_xor_sync(0xFFFFFFFF, p2, 2);
        if (tg == 0) {
            s.P[rr1 * 4 + nh] = p1;
            s.P[rr2 * 4 + nh] = p2;
        }
    }
    __syncthreads();

    // coord atomics
    if (tid < 64) {
        float scal = s.P[tid * 4 + 0] + s.P[tid * 4 + 1] + s.P[tid * 4 + 2] +
                     s.P[tid * 4 + 3] + __ldg(bc2);
        int ri = s.rowI[tid];
        atomicAdd(&g_aggC[ri * 3 + 0], s.cd[tid * 3 + 0] * scal);
        atomicAdd(&g_aggC[ri * 3 + 1], s.cd[tid * 3 + 1] * scal);
        atomicAdd(&g_aggC[ri * 3 + 2], s.cd[tid * 3 + 2] * scal);
        atomicAdd(&g_cnt[ri], 1.0f);
    }
}

// ---------------- node kernel ----------------
struct __align__(16) NSm { float X[64 * 260]; float B[32 * 256]; float A[64 * 33]; };

__global__ __launch_bounds__(256, 2) void node_kernel(
    const float* __restrict__ h, const float* __restrict__ coord,
    const float* __restrict__ Wn1, const float* __restrict__ bn1,
    const float* __restrict__ Wn2, const float* __restrict__ bn2,
    float* __restrict__ out) {
    extern __shared__ char smem_raw[];
    NSm& s = *reinterpret_cast<NSm*>(smem_raw);
    const int tid = threadIdx.x, tx = tid & 15, ty = tid >> 4, r0 = ty * 4;
    const int nb = blockIdx.x * 64;
    ull acc[4][8];
#pragma unroll
    for (int r = 0; r < 4; r++)
#pragma unroll
        for (int j = 0; j < 8; j++) acc[r][j] = 0ULL;
    const int rr = tid >> 2, kk = (tid & 3) * 8;
    const int nrow = nb + rr;
    const bool vA = nrow < Nn;

    for (int kc = 0; kc < 16; kc++) {
        const int kb = kc * 32;
        float4 v0 = make_float4(0.f, 0.f, 0.f, 0.f), v1 = v0;
        if (vA) {
            const float* src = (kc < 8) ? h + (size_t)nrow * 256 + kb + kk
                                        : g_aggH + (size_t)nrow * 256 + (kb - 256) + kk;
            v0 = *reinterpret_cast<const float4*>(src);
            v1 = *reinterpret_cast<const float4*>(src + 4);
        }
        float* da = &s.A[rr * 33 + kk];
        da[0] = v0.x; da[1] = v0.y; da[2] = v0.z; da[3] = v0.w;
        da[4] = v1.x; da[5] = v1.y; da[6] = v1.z; da[7] = v1.w;
        const float4* wsrc = reinterpret_cast<const float4*>(Wn1 + (size_t)kb * 256);
        float4* wdst = reinterpret_cast<float4*>(s.B);
#pragma unroll
        for (int i = 0; i < 8; i++) wdst[tid + 256 * i] = wsrc[tid + 256 * i];
        __syncthreads();
        mma_chunk<33>(&s.A[0], s.B, acc, tx, r0);
        __syncthreads();
    }
#pragma unroll
    for (int r = 0; r < 4; r++)
#pragma unroll
        for (int jj = 0; jj < 4; jj++) {
            int c0 = 4 * tx + 64 * jj;
            float2 p0 = unpack2(acc[r][2 * jj]), p1 = unpack2(acc[r][2 * jj + 1]);
            float4 o;
            o.x = silu_fast(p0.x + __ldg(&bn1[c0 + 0]));
            o.y = silu_fast(p0.y + __ldg(&bn1[c0 + 1]));
            o.z = silu_fast(p1.x + __ldg(&bn1[c0 + 2]));
            o.w = silu_fast(p1.y + __ldg(&bn1[c0 + 3]));
            *reinterpret_cast<float4*>(&s.X[(r0 + r) * 260 + c0]) = o;
            acc[r][2 * jj] = 0ULL; acc[r][2 * jj + 1] = 0ULL;
        }
    __syncthreads();
    for (int kc = 0; kc < 8; kc++) {
        const int kb = kc * 32;
        const float4* wsrc = reinterpret_cast<const float4*>(Wn2 + (size_t)kb * 256);
        float4* wdst = reinterpret_cast<float4*>(s.B);
#pragma unroll
        for (int i = 0; i < 8; i++) wdst[tid + 256 * i] = wsrc[tid + 256 * i];
        __syncthreads();
        mma_chunk<260>(&s.X[kb], s.B, acc, tx, r0);
        __syncthreads();
    }
#pragma unroll
    for (int r = 0; r < 4; r++) {
        int n = nb + r0 + r;
        if (n < Nn) {
#pragma unroll
            for (int jj = 0; jj < 4; jj++) {
                int c0 = 4 * tx + 64 * jj;
                float2 p0 = unpack2(acc[r][2 * jj]), p1 = unpack2(acc[r][2 * jj + 1]);
                float4 o;
                o.x = p0.x + __ldg(&bn2[c0 + 0]); o.y = p0.y + __ldg(&bn2[c0 + 1]);
                o.z = p1.x + __ldg(&bn2[c0 + 2]); o.w = p1.y + __ldg(&bn2[c0 + 3]);
                *reinterpret_cast<float4*>(&out[(size_t)n * 256 + c0]) = o;
            }
        }
    }
    if (tid < 64) {
        int n = nb + tid;
        if (n < Nn) {
            float inv = 1.0f / fmaxf(g_cnt[n], 1.0f);
#pragma unroll
            for (int dd = 0; dd < 3; dd++)
                out[(size_t)Nn * 256 + n * 3 + dd] = coord[n * 3 + dd] + g_aggC[n * 3 + dd] * inv;
        }
    }
}

// ---------------------------------------------------------------------------
extern "C" void kernel_launch(void* const* d_in, const int* in_sizes, int n_in,
                              void* d_out, int out_size) {
    const float* h     = (const float*)d_in[0];
    const float* coord = (const float*)d_in[1];
    const int*   ei    = (const int*)d_in[2];
    const float* We1   = (const float*)d_in[3];
    const float* be1   = (const float*)d_in[4];
    const float* We2   = (const float*)d_in[5];
    const float* be2   = (const float*)d_in[6];
    const float* Wn1   = (const float*)d_in[7];
    const float* bn1   = (const float*)d_in[8];
    const float* Wn2   = (const float*)d_in[9];
    const float* bn2   = (const float*)d_in[10];
    const float* Wc1   = (const float*)d_in[11];
    const float* bc1   = (const float*)d_in[12];
    const float* Wc2   = (const float*)d_in[13];
    const float* bc2   = (const float*)d_in[14];
    float* out = (float*)d_out;

    cudaFuncSetAttribute(edge_kernel, cudaFuncAttributeMaxDynamicSharedMemorySize, (int)sizeof(ESm));
    cudaFuncSetAttribute(node_kernel, cudaFuncAttributeMaxDynamicSharedMemorySize, (int)sizeof(NSm));
    cudaFuncSetAttribute(pcomp_kernel, cudaFuncAttributeMaxDynamicSharedMemorySize, (int)sizeof(PSm));

    zero_kernel<<<1280, 256>>>();
    prep_w<<<256, 256>>>(We2, 1);
    prep_w<<<256, 256>>>(Wc1, 2);
    pcomp_kernel<<<dim3((Nn + 63) / 64, 2), 256, sizeof(PSm)>>>(h, We1);
    edge_kernel<<<Ee / 64, 512, sizeof(ESm)>>>(coord, ei, We1, be1, be2, bc1, Wc2, bc2);
    node_kernel<<<(Nn + 63) / 64, 256, sizeof(NSm)>>>(h, coord, Wn1, bn1, Wn2, bn2, out);
}

// round 17
// speedup vs baseline: 1.9846x; 1.0784x over previous
#include <cuda_runtime.h>
#include <cuda_fp16.h>
#include <cstdint>

#define Nn 10000
#define Ee 320000

typedef unsigned long long ull;
typedef unsigned int u32;

// ---------------- device scratch ----------------
__device__ float g_aggH[Nn * 256];
__device__ float g_aggC[Nn * 3];
__device__ float g_cnt[Nn];
__device__ __align__(16) __half g_Ph[(size_t)Nn * 512];
__device__ __align__(16) __half g_W2h[256 * 256];
__device__ __align__(16) __half g_Wch[256 * 256];
__device__ __align__(16) __half g_N1h[256 * 512];
__device__ __align__(16) __half g_N1l[256 * 512];
__device__ __align__(16) __half g_N2h[256 * 256];
__device__ __align__(16) __half g_N2l[256 * 256];

// ---------------- helpers ----------------
__device__ __forceinline__ u32 smem_u32(const void* p) {
    u32 a;
    asm("{ .reg .u64 t; cvta.to.shared.u64 t, %1; cvt.u32.u64 %0, t; }" : "=r"(a) : "l"(p));
    return a;
}
__device__ __forceinline__ void ldsm4(u32* r, u32 addr) {
    asm volatile("ldmatrix.sync.aligned.m8n8.x4.shared.b16 {%0,%1,%2,%3},[%4];"
                 : "=r"(r[0]), "=r"(r[1]), "=r"(r[2]), "=r"(r[3]) : "r"(addr));
}
__device__ __forceinline__ void mma16816(float* d, const u32* a, const u32* b) {
    asm volatile(
        "mma.sync.aligned.m16n8k16.row.col.f32.f16.f16.f32 "
        "{%0,%1,%2,%3},{%4,%5,%6,%7},{%8,%9},{%0,%1,%2,%3};"
        : "+f"(d[0]), "+f"(d[1]), "+f"(d[2]), "+f"(d[3])
        : "r"(a[0]), "r"(a[1]), "r"(a[2]), "r"(a[3]), "r"(b[0]), "r"(b[1]));
}

// HW silu: ex2.approx + rcp.approx
__device__ __forceinline__ float silu_fast(float x) {
    float e;
    asm("ex2.approx.f32 %0, %1;" : "=f"(e) : "f"(x * -1.4426950408889634f));
    float r;
    asm("rcp.approx.f32 %0, %1;" : "=f"(r) : "f"(1.0f + e));
    return x * r;
}

// ---------------- fp32 FFMA2 pieces (pcomp) ----------------
__device__ __forceinline__ ull pack_dup(float a) { ull r; asm("mov.b64 %0,{%1,%1};" : "=l"(r) : "f"(a)); return r; }
__device__ __forceinline__ float2 unpack2(ull v) { float2 r; asm("mov.b64 {%0,%1},%2;" : "=f"(r.x), "=f"(r.y) : "l"(v)); return r; }
__device__ __forceinline__ void fma2(ull& d, ull a, ull b) { asm("fma.rn.f32x2 %0,%1,%2,%0;" : "+l"(d) : "l"(a), "l"(b)); }

template <int AS>
__device__ __forceinline__ void mma_chunk(const float* __restrict__ A, const float* __restrict__ B,
                                          ull acc[4][8], int tx, int r0) {
#pragma unroll 8
    for (int k = 0; k < 32; k++) {
        ull ap[4];
#pragma unroll
        for (int r = 0; r < 4; r++) ap[r] = pack_dup(A[(r0 + r) * AS + k]);
        const float* brow = B + k * 256 + 4 * tx;
#pragma unroll
        for (int jj = 0; jj < 4; jj++) {
            ulonglong2 bv = *reinterpret_cast<const ulonglong2*>(brow + 64 * jj);
#pragma unroll
            for (int r = 0; r < 4; r++) { fma2(acc[r][2 * jj], ap[r], bv.x); fma2(acc[r][2 * jj + 1], ap[r], bv.y); }
        }
    }
}

// ---------------- prep kernels ----------------
__global__ void zero_kernel() {
    int idx = blockIdx.x * 256 + threadIdx.x, stride = gridDim.x * 256;
    for (int i = idx; i < Nn * 256; i += stride) g_aggH[i] = 0.0f;
    for (int i = idx; i < Nn * 3; i += stride) g_aggC[i] = 0.0f;
    for (int i = idx; i < Nn; i += stride) g_cnt[i] = 0.0f;
}
// hi-only transpose (edge weights)
__global__ void prep_w(const float* __restrict__ W, int which) {
    int i = blockIdx.x * 256 + threadIdx.x;
    if (i >= 256 * 256) return;
    int k = i >> 8, n = i & 255;
    __half hb = __float2half_rn(W[i]);
    if (which == 1) g_W2h[(size_t)n * 256 + k] = hb;
    else            g_Wch[(size_t)n * 256 + k] = hb;
}
// hi+lo transpose (node weights), W [K][256] -> [256][K]
__global__ void prep_wsplit(const float* __restrict__ W, int K, int which) {
    int i = blockIdx.x * 256 + threadIdx.x;
    if (i >= K * 256) return;
    int k = i >> 8, n = i & 255;
    float v = W[i];
    __half hb = __float2half_rn(v);
    __half lb = __float2half_rn(v - __half2float(hb));
    if (which == 0) { g_N1h[(size_t)n * K + k] = hb; g_N1l[(size_t)n * K + k] = lb; }
    else            { g_N2h[(size_t)n * K + k] = hb; g_N2l[(size_t)n * K + k] = lb; }
}

// ---------------- P = h @ [We1_top | We1_bot]  (fp32 math, fp16 store) ----------------
struct __align__(16) PSm { float B[32 * 256]; float A[64 * 33]; };
__global__ __launch_bounds__(256, 2) void pcomp_kernel(const float* __restrict__ h,
                                                       const float* __restrict__ We1) {
    extern __shared__ char smr[];
    PSm& s = *reinterpret_cast<PSm*>(smr);
    const int tid = threadIdx.x, tx = tid & 15, ty = tid >> 4, r0 = ty * 4;
    const int nb = blockIdx.x * 64, hy = blockIdx.y;
    ull acc[4][8];
#pragma unroll
    for (int r = 0; r < 4; r++)
#pragma unroll
        for (int j = 0; j < 8; j++) acc[r][j] = 0ULL;
    const int rr = tid >> 2, kk = (tid & 3) * 8;
    const int nrow = nb + rr;
    const bool vA = nrow < Nn;

    for (int kc = 0; kc < 8; kc++) {
        const int kb = kc * 32;
        float4 v0 = make_float4(0.f, 0.f, 0.f, 0.f), v1 = v0;
        if (vA) {
            const float* src = h + (size_t)nrow * 256 + kb + kk;
            v0 = *reinterpret_cast<const float4*>(src);
            v1 = *reinterpret_cast<const float4*>(src + 4);
        }
        float* da = &s.A[rr * 33 + kk];
        da[0] = v0.x; da[1] = v0.y; da[2] = v0.z; da[3] = v0.w;
        da[4] = v1.x; da[5] = v1.y; da[6] = v1.z; da[7] = v1.w;
        const float4* wsrc = reinterpret_cast<const float4*>(We1 + (size_t)(hy * 256 + kb) * 256);
        float4* wdst = reinterpret_cast<float4*>(s.B);
#pragma unroll
        for (int i = 0; i < 8; i++) wdst[tid + 256 * i] = wsrc[tid + 256 * i];
        __syncthreads();
        mma_chunk<33>(&s.A[0], s.B, acc, tx, r0);
        __syncthreads();
    }
#pragma unroll
    for (int r = 0; r < 4; r++) {
        int n = nb + r0 + r;
        if (n < Nn) {
#pragma unroll
            for (int jj = 0; jj < 4; jj++) {
                int c0 = 4 * tx + 64 * jj;
                float2 p0 = unpack2(acc[r][2 * jj]), p1 = unpack2(acc[r][2 * jj + 1]);
                __half2* dst = (__half2*)&g_Ph[(size_t)n * 512 + hy * 256 + c0];
                dst[0] = __halves2half2(__float2half_rn(p0.x), __float2half_rn(p0.y));
                dst[1] = __halves2half2(__float2half_rn(p1.x), __float2half_rn(p1.y));
            }
        }
    }
}

// ---------------- fused edge kernel: 64 edges, 512 threads, occ 2 ----------------
struct __align__(128) ESm {
    __half Xh[64 * 264];
    __half BH[2][256 * 40];
    float w512[256], vbe1[256], vbe2[256], vbc1[256], vwc2[256];
    float rad[64], cd[192], P[256];
    int rowI[64], colI[64];
};

__global__ __launch_bounds__(512, 2) void edge_kernel(
    const float* __restrict__ coord, const int* __restrict__ ei,
    const float* __restrict__ We1, const float* __restrict__ be1,
    const float* __restrict__ be2, const float* __restrict__ bc1,
    const float* __restrict__ Wc2, const float* __restrict__ bc2) {
    extern __shared__ char smr[];
    ESm& s = *reinterpret_cast<ESm*>(smr);
    const int tid = threadIdx.x, wid = tid >> 5, lane = tid & 31;
    const int g = lane >> 2, tg = lane & 3;
    const int eb = blockIdx.x * 64;

    if (tid < 64) {
        int e = eb + tid;
        int ri = ei[e], ci = ei[Ee + e];
        s.rowI[tid] = ri; s.colI[tid] = ci;
        float dx = coord[ri * 3 + 0] - coord[ci * 3 + 0];
        float dy = coord[ri * 3 + 1] - coord[ci * 3 + 1];
        float dz = coord[ri * 3 + 2] - coord[ci * 3 + 2];
        s.cd[tid * 3 + 0] = dx; s.cd[tid * 3 + 1] = dy; s.cd[tid * 3 + 2] = dz;
        s.rad[tid] = dx * dx + dy * dy + dz * dz;
    }
    if (tid < 256) {
        s.w512[tid] = We1[512 * 256 + tid];
        s.vbe1[tid] = be1[tid];
        s.vbe2[tid] = be2[tid];
        s.vbc1[tid] = bc1[tid];
        s.vwc2[tid] = Wc2[tid];
    }
    __syncthreads();

    // ---- phase 1 (fp16 P gather): X = silu(P[row]+P[col|256]+rad*w512+be1) ----
    {
        int e = tid >> 3, w8 = tid & 7;
        const uint4* pr = (const uint4*)(g_Ph + (size_t)s.rowI[e] * 512) + w8;
        const uint4* pc = (const uint4*)(g_Ph + (size_t)s.colI[e] * 512 + 256) + w8;
        float radr = s.rad[e];
#pragma unroll
        for (int jj = 0; jj < 4; jj++) {
            uint4 va = pr[jj * 8], vb = pc[jj * 8];
            const __half2* ha = (const __half2*)&va;
            const __half2* hb = (const __half2*)&vb;
            int c = w8 * 8 + jj * 64;
#pragma unroll
            for (int q = 0; q < 4; q++) {
                float2 a = __half22float2(ha[q]);
                float2 b = __half22float2(hb[q]);
                int cc = c + q * 2;
                float o0 = silu_fast(a.x + b.x + radr * s.w512[cc] + s.vbe1[cc]);
                float o1 = silu_fast(a.y + b.y + radr * s.w512[cc + 1] + s.vbe1[cc + 1]);
                *reinterpret_cast<__half2*>(&s.Xh[e * 264 + cc]) =
                    __halves2half2(__float2half_rn(o0), __float2half_rn(o1));
            }
        }
    }
    __syncthreads();

    // ---- warp tiling: 4 M-groups x 4 N-quarters ----
    const int mwid = wid & 3, nh = wid >> 2;
    const int aRow = (lane & 7) + (lane & 8);
    const int aK8 = (lane & 16) ? 8 : 0;
    const int bRow = (lane & 7) + ((lane & 16) ? 8 : 0);
    const int bK8 = (lane & 8) ? 8 : 0;
    const u32 xh_b = smem_u32(s.Xh);
    const u32 aoff = ((u32)(mwid * 16 + aRow) * 264 + aK8) * 2;
    const u32 bOff = ((u32)(nh * 64 + bRow) * 40 + bK8) * 2;
    const u32 bh_b0 = smem_u32(s.BH[0]) + bOff, bh_b1 = smem_u32(s.BH[1]) + bOff;
    const int sn = tid >> 1, sh = tid & 1;
    const int rr1 = mwid * 16 + g, rr2 = rr1 + 8;

    float d[8][4];

    // =========================== GEMM2 (We2, 1-term) ===========================
    {
#pragma unroll
        for (int i = 0; i < 8; i++)
#pragma unroll
            for (int j = 0; j < 4; j++) d[i][j] = 0.0f;

        uint4 pb0, pb1;
        auto loadB = [&](int kc) {
            const uint4* b4 = (const uint4*)(g_W2h + (size_t)sn * 256 + kc * 32 + sh * 16);
            pb0 = b4[0]; pb1 = b4[1];
        };
        auto storeB = [&](int b) {
            *(uint4*)&s.BH[b][sn * 40 + sh * 16] = pb0;
            *(uint4*)&s.BH[b][sn * 40 + sh * 16 + 8] = pb1;
        };
        loadB(0); storeB(0);
        __syncthreads();

        for (int kc = 0; kc < 8; kc++) {
            if (kc < 7) loadB(kc + 1);
            const u32 bb = (kc & 1) ? bh_b1 : bh_b0;
#pragma unroll
            for (int ks = 0; ks < 2; ks++) {
                u32 a[4];
                ldsm4(a, xh_b + aoff + (kc * 32 + ks * 16) * 2);
#pragma unroll
                for (int ng = 0; ng < 4; ng++) {
                    u32 bh[4];
                    ldsm4(bh, bb + ng * 1280 + ks * 32);
                    mma16816(d[2 * ng], a, bh);
                    mma16816(d[2 * ng + 1], a, bh + 2);
                }
            }
            if (kc < 7) storeB((kc + 1) & 1);
            __syncthreads();
        }

        int ri1 = s.rowI[rr1], ri2 = s.rowI[rr2];
#pragma unroll
        for (int ng = 0; ng < 4; ng++) {
#pragma unroll
            for (int hf = 0; hf < 2; hf++) {
                int c = nh * 64 + ng * 16 + hf * 8 + tg * 2;
                float* dd = d[2 * ng + hf];
                float o0 = silu_fast(dd[0] + s.vbe2[c]);
                float o1 = silu_fast(dd[1] + s.vbe2[c + 1]);
                float o2 = silu_fast(dd[2] + s.vbe2[c]);
                float o3 = silu_fast(dd[3] + s.vbe2[c + 1]);
                atomicAdd((float2*)&g_aggH[(size_t)ri1 * 256 + c], make_float2(o0, o1));
                atomicAdd((float2*)&g_aggH[(size_t)ri2 * 256 + c], make_float2(o2, o3));
                *reinterpret_cast<__half2*>(&s.Xh[rr1 * 264 + c]) =
                    __halves2half2(__float2half_rn(o0), __float2half_rn(o1));
                *reinterpret_cast<__half2*>(&s.Xh[rr2 * 264 + c]) =
                    __halves2half2(__float2half_rn(o2), __float2half_rn(o3));
            }
        }
    }
    __syncthreads();

    // =========================== GEMM3 (Wc1, 1-term) ===========================
    {
#pragma unroll
        for (int i = 0; i < 8; i++)
#pragma unroll
            for (int j = 0; j < 4; j++) d[i][j] = 0.0f;

        uint4 pb0, pb1;
        auto loadB = [&](int kc) {
            const uint4* b4 = (const uint4*)(g_Wch + (size_t)sn * 256 + kc * 32 + sh * 16);
            pb0 = b4[0]; pb1 = b4[1];
        };
        auto storeB = [&](int b) {
            *(uint4*)&s.BH[b][sn * 40 + sh * 16] = pb0;
            *(uint4*)&s.BH[b][sn * 40 + sh * 16 + 8] = pb1;
        };
        loadB(0); storeB(0);
        __syncthreads();

        for (int kc = 0; kc < 8; kc++) {
            if (kc < 7) loadB(kc + 1);
            const u32 bb = (kc & 1) ? bh_b1 : bh_b0;
#pragma unroll
            for (int ks = 0; ks < 2; ks++) {
                u32 a[4];
                ldsm4(a, xh_b + aoff + (kc * 32 + ks * 16) * 2);
#pragma unroll
                for (int ng = 0; ng < 4; ng++) {
                    u32 bh[4];
                    ldsm4(bh, bb + ng * 1280 + ks * 32);
                    mma16816(d[2 * ng], a, bh);
                    mma16816(d[2 * ng + 1], a, bh + 2);
                }
            }
            if (kc < 7) storeB((kc + 1) & 1);
            __syncthreads();
        }

        float p1 = 0.0f, p2 = 0.0f;
#pragma unroll
        for (int ng = 0; ng < 4; ng++) {
#pragma unroll
            for (int hf = 0; hf < 2; hf++) {
                int c = nh * 64 + ng * 16 + hf * 8 + tg * 2;
                float* dd = d[2 * ng + hf];
                p1 = fmaf(silu_fast(dd[0] + s.vbc1[c]), s.vwc2[c], p1);
                p1 = fmaf(silu_fast(dd[1] + s.vbc1[c + 1]), s.vwc2[c + 1], p1);
                p2 = fmaf(silu_fast(dd[2] + s.vbc1[c]), s.vwc2[c], p2);
                p2 = fmaf(silu_fast(dd[3] + s.vbc1[c + 1]), s.vwc2[c + 1], p2);
            }
        }
        p1 += __shfl_xor_sync(0xFFFFFFFF, p1, 1);
        p1 += __shfl_xor_sync(0xFFFFFFFF, p1, 2);
        p2 += __shfl_xor_sync(0xFFFFFFFF, p2, 1);
        p2 += __shfl_xor_sync(0xFFFFFFFF, p2, 2);
        if (tg == 0) {
            s.P[rr1 * 4 + nh] = p1;
            s.P[rr2 * 4 + nh] = p2;
        }
    }
    __syncthreads();

    if (tid < 64) {
        float scal = s.P[tid * 4 + 0] + s.P[tid * 4 + 1] + s.P[tid * 4 + 2] +
                     s.P[tid * 4 + 3] + __ldg(bc2);
        int ri = s.rowI[tid];
        atomicAdd(&g_aggC[ri * 3 + 0], s.cd[tid * 3 + 0] * scal);
        atomicAdd(&g_aggC[ri * 3 + 1], s.cd[tid * 3 + 1] * scal);
        atomicAdd(&g_aggC[ri * 3 + 2], s.cd[tid * 3 + 2] * scal);
        atomicAdd(&g_cnt[ri], 1.0f);
    }
}

// ---------------- node kernel: HMMA, 64 nodes, 512 threads, occ 2 ----------------
struct __align__(128) NSm {
    __half Xn[64 * 264];        // A tile (K=256 view)
    __half BH[2][256 * 24];     // double-buffered hi
    __half BL[2][256 * 24];     // double-buffered lo
    float vb1[256];
};

__global__ __launch_bounds__(512, 2) void node_kernel(
    const float* __restrict__ h, const float* __restrict__ coord,
    const float* __restrict__ bn1, const float* __restrict__ bn2,
    float* __restrict__ out) {
    extern __shared__ char smr[];
    NSm& s = *reinterpret_cast<NSm*>(smr);
    const int tid = threadIdx.x, wid = tid >> 5, lane = tid & 31;
    const int g = lane >> 2, tg = lane & 3;
    const int nb = blockIdx.x * 64;

    if (tid < 256) s.vb1[tid] = bn1[tid];

    const int mwid = wid & 3, nh = wid >> 2;
    const int aRow = (lane & 7) + (lane & 8);
    const int aK8 = (lane & 16) ? 8 : 0;
    const int bRow = (lane & 7) + ((lane & 16) ? 8 : 0);
    const int bK8 = (lane & 8) ? 8 : 0;
    const u32 xn_b = smem_u32(s.Xn);
    const u32 aoff = ((u32)(mwid * 16 + aRow) * 264 + aK8) * 2;
    const u32 bOff = ((u32)(nh * 64 + bRow) * 24 + bK8) * 2;
    const u32 bh_b0 = smem_u32(s.BH[0]) + bOff, bh_b1 = smem_u32(s.BH[1]) + bOff;
    const u32 bl_b0 = smem_u32(s.BL[0]) + bOff, bl_b1 = smem_u32(s.BL[1]) + bOff;
    const int sn = tid >> 1, sh = tid & 1;
    const int rr1 = mwid * 16 + g, rr2 = rr1 + 8;

    // stage A tile from fp32 source (guarded); FULL 256 columns per row
    auto stageA = [&](const float* src) {
        int r = tid >> 3, w8 = tid & 7;
        int n = nb + r;
#pragma unroll
        for (int jj = 0; jj < 8; jj++) {
            float4 v = make_float4(0.f, 0.f, 0.f, 0.f);
            if (n < Nn) v = *(const float4*)(src + (size_t)n * 256 + w8 * 4 + jj * 32);
            int c = w8 * 4 + jj * 32;
            *(__half2*)&s.Xn[r * 264 + c] =
                __halves2half2(__float2half_rn(v.x), __float2half_rn(v.y));
            *(__half2*)&s.Xn[r * 264 + c + 2] =
                __halves2half2(__float2half_rn(v.z), __float2half_rn(v.w));
        }
    };

    float d[8][4];
#pragma unroll
    for (int i = 0; i < 8; i++)
#pragma unroll
        for (int j = 0; j < 4; j++) d[i][j] = 0.0f;

    // GEMM over one K=256 segment of [Wh|Wl] (stride floats), accumulating d
    auto runGemm = [&](const __half* Wh, const __half* Wl, int stride, int kofs) {
        uint4 pbh, pbl;
        auto loadB = [&](int kc) {
            pbh = *(const uint4*)(Wh + (size_t)sn * stride + kofs + kc * 16 + sh * 8);
            pbl = *(const uint4*)(Wl + (size_t)sn * stride + kofs + kc * 16 + sh * 8);
        };
        auto storeB = [&](int b) {
            *(uint4*)&s.BH[b][sn * 24 + sh * 8] = pbh;
            *(uint4*)&s.BL[b][sn * 24 + sh * 8] = pbl;
        };
        loadB(0); storeB(0);
        __syncthreads();
        for (int kc = 0; kc < 16; kc++) {
            if (kc < 15) loadB(kc + 1);
            const u32 bh_b = (kc & 1) ? bh_b1 : bh_b0;
            const u32 bl_b = (kc & 1) ? bl_b1 : bl_b0;
            u32 a[4];
            ldsm4(a, xn_b + aoff + kc * 32);
#pragma unroll
            for (int ng = 0; ng < 4; ng++) {
                u32 bh[4], bl[4];
                ldsm4(bh, bh_b + ng * 768);
                ldsm4(bl, bl_b + ng * 768);
                mma16816(d[2 * ng], a, bh);
                mma16816(d[2 * ng], a, bl);
                mma16816(d[2 * ng + 1], a, bh + 2);
                mma16816(d[2 * ng + 1], a, bl + 2);
            }
            if (kc < 15) storeB((kc + 1) & 1);
            __syncthreads();
        }
    };

    // ---- GEMM-N1a: h @ Wn1_top ----
    stageA(h);
    __syncthreads();
    runGemm(g_N1h, g_N1l, 512, 0);

    // ---- GEMM-N1b: aggH @ Wn1_bot (accumulate) ----
    stageA(g_aggH);
    __syncthreads();
    runGemm(g_N1h, g_N1l, 512, 256);

    // ---- epilogue N1: silu -> Xn ----
#pragma unroll
    for (int ng = 0; ng < 4; ng++) {
#pragma unroll
        for (int hf = 0; hf < 2; hf++) {
            int c = nh * 64 + ng * 16 + hf * 8 + tg * 2;
            float* dd = d[2 * ng + hf];
            float o0 = silu_fast(dd[0] + s.vb1[c]);
            float o1 = silu_fast(dd[1] + s.vb1[c + 1]);
            float o2 = silu_fast(dd[2] + s.vb1[c]);
            float o3 = silu_fast(dd[3] + s.vb1[c + 1]);
            *reinterpret_cast<__half2*>(&s.Xn[rr1 * 264 + c]) =
                __halves2half2(__float2half_rn(o0), __float2half_rn(o1));
            *reinterpret_cast<__half2*>(&s.Xn[rr2 * 264 + c]) =
                __halves2half2(__float2half_rn(o2), __float2half_rn(o3));
            dd[0] = 0.f; dd[1] = 0.f; dd[2] = 0.f; dd[3] = 0.f;
        }
    }
    __syncthreads();

    // ---- GEMM-N2: X2 @ Wn2 ----
    runGemm(g_N2h, g_N2l, 256, 0);

    // ---- epilogue N2: + bn2 -> out ----
    {
        int n1 = nb + rr1, n2 = nb + rr2;
#pragma unroll
        for (int ng = 0; ng < 4; ng++) {
#pragma unroll
            for (int hf = 0; hf < 2; hf++) {
                int c = nh * 64 + ng * 16 + hf * 8 + tg * 2;
                float* dd = d[2 * ng + hf];
                float b0 = __ldg(&bn2[c]), b1 = __ldg(&bn2[c + 1]);
                if (n1 < Nn)
                    *(float2*)&out[(size_t)n1 * 256 + c] = make_float2(dd[0] + b0, dd[1] + b1);
                if (n2 < Nn)
                    *(float2*)&out[(size_t)n2 * 256 + c] = make_float2(dd[2] + b0, dd[3] + b1);
            }
        }
    }

    // coord epilogue
    if (tid < 64) {
        int n = nb + tid;
        if (n < Nn) {
            float inv = 1.0f / fmaxf(g_cnt[n], 1.0f);
#pragma unroll
            for (int dd = 0; dd < 3; dd++)
                out[(size_t)Nn * 256 + n * 3 + dd] = coord[n * 3 + dd] + g_aggC[n * 3 + dd] * inv;
        }
    }
}

// ---------------------------------------------------------------------------
extern "C" void kernel_launch(void* const* d_in, const int* in_sizes, int n_in,
                              void* d_out, int out_size) {
    const float* h     = (const float*)d_in[0];
    const float* coord = (const float*)d_in[1];
    const int*   ei    = (const int*)d_in[2];
    const float* We1   = (const float*)d_in[3];
    const float* be1   = (const float*)d_in[4];
    const float* We2   = (const float*)d_in[5];
    const float* be2   = (const float*)d_in[6];
    const float* Wn1   = (const float*)d_in[7];
    const float* bn1   = (const float*)d_in[8];
    const float* Wn2   = (const float*)d_in[9];
    const float* bn2   = (const float*)d_in[10];
    const float* Wc1   = (const float*)d_in[11];
    const float* bc1   = (const float*)d_in[12];
    const float* Wc2   = (const float*)d_in[13];
    const float* bc2   = (const float*)d_in[14];
    float* out = (float*)d_out;

    cudaFuncSetAttribute(edge_kernel, cudaFuncAttributeMaxDynamicSharedMemorySize, (int)sizeof(ESm));
    cudaFuncSetAttribute(node_kernel, cudaFuncAttributeMaxDynamicSharedMemorySize, (int)sizeof(NSm));
    cudaFuncSetAttribute(pcomp_kernel, cudaFuncAttributeMaxDynamicSharedMemorySize, (int)sizeof(PSm));

    zero_kernel<<<1280, 256>>>();
    prep_w<<<256, 256>>>(We2, 1);
    prep_w<<<256, 256>>>(Wc1, 2);
    prep_wsplit<<<512, 256>>>(Wn1, 512, 0);
    prep_wsplit<<<256, 256>>>(Wn2, 256, 1);
    pcomp_kernel<<<dim3((Nn + 63) / 64, 2), 256, sizeof(PSm)>>>(h, We1);
    edge_kernel<<<Ee / 64, 512, sizeof(ESm)>>>(coord, ei, We1, be1, be2, bc1, Wc2, bc2);
    node_kernel<<<(Nn + 63) / 64, 512, sizeof(NSm)>>>(h, coord, bn1, bn2, out);
}